// round 11
// baseline (speedup 1.0000x reference)
#include <cuda_runtime.h>
#include <cstdint>

#define NMAX 4096
#define HID 64

typedef unsigned long long ull;

// ---------------- device scratch ----------------
__device__ __align__(256) float g_P[NMAX * HID];
__device__ __align__(256) float g_agg[NMAX * HID];
__device__ __align__(256) float g_q[4 * NMAX * 16];
__device__ __align__(256) float g_k[4 * NMAX * 16];
__device__ __align__(256) float g_v[4 * NMAX * 16];
__device__ __align__(256) float g_obuf[NMAX * HID];
__device__ __align__(256) float g_wgk[64 * 64];  // [k][d] = w2[d][k]*g[k] (scalar)
__device__ __align__(256) float g_A[64];         // A[d] = sum_k w2[d][k]*g[k]
__device__ __align__(256) float g_Bc[64];        // B[d] + b2[d]
__device__ int g_is64_ei;
__device__ int g_is64_ty;

__device__ __forceinline__ long ldidx(const void* p, long i, int is64) {
    return is64 ? (long)((const long long*)p)[i] : (long)((const int*)p)[i];
}

// ---------------- packed f32x2 helpers ----------------
__device__ __forceinline__ ull pack2(float lo, float hi) {
    ull r; asm("mov.b64 %0, {%1, %2};" : "=l"(r) : "f"(lo), "f"(hi)); return r;
}
__device__ __forceinline__ void unpack2(ull v, float& lo, float& hi) {
    asm("mov.b64 {%0, %1}, %2;" : "=f"(lo), "=f"(hi) : "l"(v));
}
__device__ __forceinline__ void ffma2(ull& d, ull a, ull b) {
    asm("fma.rn.f32x2 %0, %1, %2, %0;" : "+l"(d) : "l"(a), "l"(b));
}
__device__ __forceinline__ ull mul2(ull a, ull b) {
    ull r; asm("mul.rn.f32x2 %0, %1, %2;" : "=l"(r) : "l"(a), "l"(b)); return r;
}
__device__ __forceinline__ float ex2f(float x) {
    float r; asm("ex2.approx.ftz.f32 %0, %1;" : "=f"(r) : "f"(x)); return r;
}

// ---------------- detect dtypes + per-dim LN1-fold constants ----------------
__global__ void detectAB_kernel(const unsigned* ei, const unsigned* ty,
                                const float* __restrict__ w2g,
                                const float* __restrict__ lng,
                                const float* __restrict__ lnb,
                                const float* __restrict__ b2) {
    int d = threadIdx.x;   // 64
    float A = 0.f, B = 0.f;
#pragma unroll 8
    for (int k = 0; k < 64; k++) {
        float w = w2g[d * 64 + k];
        A = fmaf(w, lng[k], A);
        B = fmaf(w, lnb[k], B);
    }
    g_A[d] = A;
    g_Bc[d] = B + b2[d];
    if (d == 0) {
        unsigned a = 0;
        for (int i = 0; i < 32; i++) a |= ei[2 * i + 1];
        g_is64_ei = (a == 0) ? 1 : 0;
        unsigned b = 0;
        for (int i = 0; i < 32; i++) b |= ty[2 * i + 1];
        g_is64_ty = (b == 0) ? 1 : 0;
    }
}

// ---------------- fused setup: zero g_agg | pack w*g k-major | prep P -------
__global__ void __launch_bounds__(256) setup_kernel(
    const float* __restrict__ x, const float* __restrict__ emb,
    const float* __restrict__ w1, const float* __restrict__ b1,
    const void* __restrict__ ety, const float* __restrict__ w2g,
    const float* __restrict__ lng, int N) {
    int bid = blockIdx.x, t = threadIdx.x;
    int zb = N / 16;
    if (bid < zb) {
        ((float4*)g_agg)[bid * 256 + t] = make_float4(0.f, 0.f, 0.f, 0.f);
    } else if (bid < zb + 16) {
        int i = (bid - zb) * 256 + t;        // i = k*64 + d
        int k = i >> 6, d = i & 63;
        g_wgk[i] = w2g[d * 64 + k] * lng[k];
    } else {
        int nb = bid - zb - 16;
        int grp = t >> 6, d = t & 63;
        int n = nb * 4 + grp;
        __shared__ float xs[4][16];
        int is64 = g_is64_ty;
        if (d < 6) {
            xs[grp][d] = x[n * 6 + d];
        } else if (d < 14) {
            long tt = ldidx(ety, n, is64);
            xs[grp][d] = emb[tt * 8 + (d - 6)];
        }
        __syncthreads();
        float acc = b1[d];
#pragma unroll
        for (int k = 0; k < 14; k++) acc = fmaf(xs[grp][k], w1[d * 15 + k], acc);
        g_P[n * HID + d] = acc;
    }
}

// ---------------- edge MLP + scatter-add ------------------------------------
// 128 threads / 128 edges. Stage B: warp = 16-dim group; weight pairs are
// consecutive scalar floats read broadcast; h duplicated in-reg (4 pack2/k).
// Stage C: TWO-PASS over packed acc (no vv materialization -> no spills).
#define EDGE_DYN (32768 + 16384)
__global__ void __launch_bounds__(128, 4) edge_kernel(
    const void* __restrict__ ei, const float* __restrict__ eattr,
    const float* __restrict__ w1, const float* __restrict__ lng,
    const float* __restrict__ lnb, int nE) {
    extern __shared__ __align__(16) char dyn[];
    float* h1f = (float*)dyn;                 // 32KB [k][128]; overlaid later
    float* w2s = (float*)(dyn + 32768);       // 16KB [k][64] scalar w*g
    __shared__ __align__(16) float w1ls[64];
    __shared__ __align__(16) float As[64];
    __shared__ __align__(16) float Bcs[64];
    __shared__ __align__(16) float gs[64];
    __shared__ __align__(16) float bs[64];
    __shared__ __align__(8) float rst[128 * 2];
    __shared__ int sdst[128];

    int tid = threadIdx.x;
    {   // stage scalar weights: 1024 float4 over 128 threads
        const float4* wsrc = (const float4*)g_wgk;
        float4* wdst = (float4*)w2s;
#pragma unroll
        for (int i = 0; i < 8; i++) wdst[i * 128 + tid] = wsrc[i * 128 + tid];
    }
    if (tid < 64) {
        w1ls[tid] = w1[tid * 15 + 14];
        As[tid] = g_A[tid];
        Bcs[tid] = g_Bc[tid];
        gs[tid] = lng[tid];
        bs[tid] = lnb[tid];
    }
    long e = (long)blockIdx.x * 128 + tid;
    bool act = e < nE;
    int is64 = g_is64_ei;
    long src = 0;
    float a = 0.f;
    {
        long dl = -1;
        if (act) {
            src = ldidx(ei, e, is64);
            dl = ldidx(ei, (long)nE + e, is64);
            a = eattr[e];
        }
        sdst[tid] = (int)dl;
    }
    __syncthreads();

    // ---- Stage A: x = relu(P[src] + a*w1_last); stats; raw x -> smem ----
    {
        const float4* pr = (const float4*)(g_P + src * 64);
        float s1 = 0.f, q1 = 0.f;
#pragma unroll
        for (int g = 0; g < 16; g++) {
            float4 p = pr[g];
            float4 wl = ((const float4*)w1ls)[g];
            float x0 = fmaxf(fmaf(a, wl.x, p.x), 0.f);
            float x1 = fmaxf(fmaf(a, wl.y, p.y), 0.f);
            float x2 = fmaxf(fmaf(a, wl.z, p.z), 0.f);
            float x3 = fmaxf(fmaf(a, wl.w, p.w), 0.f);
            h1f[(4 * g + 0) * 128 + tid] = x0;
            h1f[(4 * g + 1) * 128 + tid] = x1;
            h1f[(4 * g + 2) * 128 + tid] = x2;
            h1f[(4 * g + 3) * 128 + tid] = x3;
            s1 += (x0 + x1) + (x2 + x3);
            q1 = fmaf(x0, x0, q1); q1 = fmaf(x1, x1, q1);
            q1 = fmaf(x2, x2, q1); q1 = fmaf(x3, x3, q1);
        }
        float mean1 = s1 * (1.f / 64.f);
        float var1 = fmaf(-mean1, mean1, q1 * (1.f / 64.f));
        float r1 = rsqrtf(var1 + 1e-5f);
        rst[2 * tid] = r1;
        rst[2 * tid + 1] = -mean1 * r1;
    }
    __syncthreads();

    // ---- Stage B: acc over dim-pairs; w pairs native, h duplicated ----
    int lane = tid & 31, wrp = tid >> 5;
    ull acc[4][8];   // [edge 0..3][dim-pair 0..7], dims = wrp*16 + 2*jp (+1)
#pragma unroll
    for (int ee = 0; ee < 4; ee++)
#pragma unroll
        for (int jp = 0; jp < 8; jp++) acc[ee][jp] = 0ull;
    {
        const float4* hb4 = (const float4*)h1f;
        const float* wbase = w2s + wrp * 16;
#pragma unroll 8
        for (int k = 0; k < 64; k++) {
            float4 hv = hb4[k * 32 + lane];        // edges 4*lane..+3, coalesced
            ull h0 = pack2(hv.x, hv.x);
            ull h1 = pack2(hv.y, hv.y);
            ull h2 = pack2(hv.z, hv.z);
            ull h3 = pack2(hv.w, hv.w);
            const ulonglong2* wk = (const ulonglong2*)(wbase + k * 64);
            ulonglong2 wA = wk[0];
            ulonglong2 wB = wk[1];
            ulonglong2 wC = wk[2];
            ulonglong2 wD = wk[3];
            ffma2(acc[0][0], wA.x, h0); ffma2(acc[1][0], wA.x, h1);
            ffma2(acc[2][0], wA.x, h2); ffma2(acc[3][0], wA.x, h3);
            ffma2(acc[0][1], wA.y, h0); ffma2(acc[1][1], wA.y, h1);
            ffma2(acc[2][1], wA.y, h2); ffma2(acc[3][1], wA.y, h3);
            ffma2(acc[0][2], wB.x, h0); ffma2(acc[1][2], wB.x, h1);
            ffma2(acc[2][2], wB.x, h2); ffma2(acc[3][2], wB.x, h3);
            ffma2(acc[0][3], wB.y, h0); ffma2(acc[1][3], wB.y, h1);
            ffma2(acc[2][3], wB.y, h2); ffma2(acc[3][3], wB.y, h3);
            ffma2(acc[0][4], wC.x, h0); ffma2(acc[1][4], wC.x, h1);
            ffma2(acc[2][4], wC.x, h2); ffma2(acc[3][4], wC.x, h3);
            ffma2(acc[0][5], wC.y, h0); ffma2(acc[1][5], wC.y, h1);
            ffma2(acc[2][5], wC.y, h2); ffma2(acc[3][5], wC.y, h3);
            ffma2(acc[0][6], wD.x, h0); ffma2(acc[1][6], wD.x, h1);
            ffma2(acc[2][6], wD.x, h2); ffma2(acc[3][6], wD.x, h3);
            ffma2(acc[0][7], wD.y, h0); ffma2(acc[1][7], wD.y, h1);
            ffma2(acc[2][7], wD.y, h2); ffma2(acc[3][7], wD.y, h3);
        }
    }

    // ---- Stage C (two-pass; no vv array) ----
    float Ar[16], Br[16];
    {
        const float4* ap = (const float4*)(As + wrp * 16);
        const float4* bp = (const float4*)(Bcs + wrp * 16);
#pragma unroll
        for (int u = 0; u < 4; u++) {
            float4 av = ap[u], bv = bp[u];
            Ar[4 * u] = av.x; Ar[4 * u + 1] = av.y; Ar[4 * u + 2] = av.z; Ar[4 * u + 3] = av.w;
            Br[4 * u] = bv.x; Br[4 * u + 1] = bv.y; Br[4 * u + 2] = bv.z; Br[4 * u + 3] = bv.w;
        }
    }
    float rr[4], mm[4];
    int dn[4];
#pragma unroll
    for (int i = 0; i < 4; i++) {
        rr[i] = rst[2 * (4 * lane + i)];
        mm[i] = rst[2 * (4 * lane + i) + 1];
        dn[i] = sdst[4 * lane + i];
    }
    // pass 1: stats only (v recomputed from packed acc, not stored)
    float se[4] = {0.f, 0.f, 0.f, 0.f}, qe[4] = {0.f, 0.f, 0.f, 0.f};
#pragma unroll
    for (int ee = 0; ee < 4; ee++) {
#pragma unroll
        for (int jp = 0; jp < 8; jp++) {
            float lo, hi;
            unpack2(acc[ee][jp], lo, hi);
            int j0 = 2 * jp, j1 = 2 * jp + 1;
            float v0 = fmaxf(fmaf(rr[ee], lo, fmaf(mm[ee], Ar[j0], Br[j0])), 0.f);
            float v1 = fmaxf(fmaf(rr[ee], hi, fmaf(mm[ee], Ar[j1], Br[j1])), 0.f);
            se[ee] += v0 + v1;
            qe[ee] = fmaf(v0, v0, qe[ee]);
            qe[ee] = fmaf(v1, v1, qe[ee]);
        }
    }
    __syncthreads();   // h1f reads done; overlay partials
    float* ps = h1f;            // [4][128]
    float* pq = h1f + 512;      // [4][128]
#pragma unroll
    for (int i = 0; i < 4; i++) {
        ps[wrp * 128 + 4 * lane + i] = se[i];
        pq[wrp * 128 + 4 * lane + i] = qe[i];
    }
    __syncthreads();
    {
        float s = ps[tid] + ps[128 + tid] + ps[256 + tid] + ps[384 + tid];
        float q = pq[tid] + pq[128 + tid] + pq[256 + tid] + pq[384 + tid];
        float mean = s * (1.f / 64.f);
        float var = fmaf(-mean, mean, q * (1.f / 64.f));
        float r = rsqrtf(var + 1e-5f);
        rst[2 * tid] = r;
        rst[2 * tid + 1] = -mean * r;
    }
    __syncthreads();
    // pass 2: recompute v from acc, apply LN2 (g/b via broadcast LDS), scatter
#pragma unroll
    for (int ee = 0; ee < 4; ee++) {
        float r2 = rst[2 * (4 * lane + ee)];
        float mr2 = rst[2 * (4 * lane + ee) + 1];
        if (dn[ee] >= 0) {
            float* p = g_agg + (long)dn[ee] * 64 + wrp * 16;
#pragma unroll
            for (int u = 0; u < 4; u++) {
                int jpA = 2 * u, jpB = 2 * u + 1;
                float lo0, hi0, lo1, hi1;
                unpack2(acc[ee][jpA], lo0, hi0);
                unpack2(acc[ee][jpB], lo1, hi1);
                int j0 = 4 * u, j1 = j0 + 1, j2 = j0 + 2, j3 = j0 + 3;
                float v0 = fmaxf(fmaf(rr[ee], lo0, fmaf(mm[ee], Ar[j0], Br[j0])), 0.f);
                float v1 = fmaxf(fmaf(rr[ee], hi0, fmaf(mm[ee], Ar[j1], Br[j1])), 0.f);
                float v2 = fmaxf(fmaf(rr[ee], lo1, fmaf(mm[ee], Ar[j2], Br[j2])), 0.f);
                float v3 = fmaxf(fmaf(rr[ee], hi1, fmaf(mm[ee], Ar[j3], Br[j3])), 0.f);
                float4 gv = ((const float4*)(gs + wrp * 16))[u];
                float4 bv = ((const float4*)(bs + wrp * 16))[u];
                float o0 = fmaf(fmaf(v0, r2, mr2), gv.x, bv.x);
                float o1 = fmaf(fmaf(v1, r2, mr2), gv.y, bv.y);
                float o2 = fmaf(fmaf(v2, r2, mr2), gv.z, bv.z);
                float o3 = fmaf(fmaf(v3, r2, mr2), gv.w, bv.w);
                asm volatile("red.global.add.v4.f32 [%0], {%1,%2,%3,%4};"
                             :: "l"(p + 4 * u), "f"(o0), "f"(o1), "f"(o2), "f"(o3)
                             : "memory");
            }
        }
    }
}

// ---------------- qkv = h @ in_proj_w.T + b, 32 nodes/block ------------------
__global__ void __launch_bounds__(192) qkv_kernel(const float* __restrict__ w,
                                                  const float* __restrict__ b, int N) {
    __shared__ __align__(16) float hs[32 * 64];
    int tid = threadIdx.x;
    int n0 = blockIdx.x * 32;
    for (int i = tid; i < 32 * 64 / 4; i += 192)
        ((float4*)hs)[i] = ((const float4*)(g_agg + n0 * 64))[i];
    float wr[64];
    {
        const float4* p4 = (const float4*)(w + tid * 64);
#pragma unroll
        for (int k = 0; k < 16; k++) {
            float4 f = p4[k];
            wr[4 * k] = f.x; wr[4 * k + 1] = f.y; wr[4 * k + 2] = f.z; wr[4 * k + 3] = f.w;
        }
    }
    float br = b[tid];
    __syncthreads();
    int sec = tid / 64, wi = tid % 64, hh = wi / 16, dd = wi % 16;
    float* dst = sec == 0 ? g_q : (sec == 1 ? g_k : g_v);
#pragma unroll 4
    for (int nn = 0; nn < 32; nn++) {
        float acc = br;
#pragma unroll
        for (int k = 0; k < 16; k++) {
            float4 h = *(const float4*)&hs[nn * 64 + 4 * k];
            acc = fmaf(wr[4 * k], h.x, acc);
            acc = fmaf(wr[4 * k + 1], h.y, acc);
            acc = fmaf(wr[4 * k + 2], h.z, acc);
            acc = fmaf(wr[4 * k + 3], h.w, acc);
        }
        dst[hh * N * 16 + (n0 + nn) * 16 + dd] = acc;
    }
}

// ---------------- flash attention, f32x2, log2-domain softmax ---------------
__global__ void __launch_bounds__(128) attn_kernel(int N) {
    int hh = blockIdx.y;
    int part = threadIdx.x >> 5;
    int lane = threadIdx.x & 31;
    int qi = blockIdx.x * 32 + lane;
    const float* Q = g_q + hh * N * 16;
    const float* K = g_k + hh * N * 16;
    const float* V = g_v + hh * N * 16;

    __shared__ __align__(16) float Ks[4][64 * 16];
    __shared__ __align__(16) float Vs[4][64 * 16];
    __shared__ float mrg[3][32][18];

    // scale = (1/4) * log2(e): scores live in log2 domain; softmax unchanged.
    const float QS = 0.25f * 1.4426950408889634f;
    ull q2[8];
    {
        const float4* qp = (const float4*)(Q + qi * 16);
#pragma unroll
        for (int u = 0; u < 4; u++) {
            float4 f = qp[u];
            q2[2 * u] = pack2(f.x * QS, f.y * QS);
            q2[2 * u + 1] = pack2(f.z * QS, f.w * QS);
        }
    }
    ull o2[8];
#pragma unroll
    for (int u = 0; u < 8; u++) o2[u] = 0ull;
    float m = -1e30f, l = 0.f;

    int j0 = part * (N >> 2);
    for (int kt = 0; kt < (N >> 2); kt += 64) {
        {
            const float4* ksrc = (const float4*)(K + (j0 + kt) * 16);
            const float4* vsrc = (const float4*)(V + (j0 + kt) * 16);
            float4* kdst = (float4*)Ks[part];
            float4* vdst = (float4*)Vs[part];
#pragma unroll
            for (int u = 0; u < 8; u++) {
                kdst[u * 32 + lane] = ksrc[u * 32 + lane];
                vdst[u * 32 + lane] = vsrc[u * 32 + lane];
            }
        }
        __syncwarp();
        for (int c = 0; c < 4; c++) {
            float s[16];
#pragma unroll
            for (int jj = 0; jj < 16; jj++) {
                int j = c * 16 + jj;
                const ulonglong2* kr = (const ulonglong2*)&Ks[part][j * 16];
                ulonglong2 ka = kr[0], kb = kr[1], kc = kr[2], kd = kr[3];
                ull s2 = mul2(q2[0], ka.x);
                ffma2(s2, q2[1], ka.y);
                ffma2(s2, q2[2], kb.x);
                ffma2(s2, q2[3], kb.y);
                ffma2(s2, q2[4], kc.x);
                ffma2(s2, q2[5], kc.y);
                ffma2(s2, q2[6], kd.x);
                ffma2(s2, q2[7], kd.y);
                float slo, shi;
                unpack2(s2, slo, shi);
                s[jj] = slo + shi;
            }
            float tm = s[0];
#pragma unroll
            for (int jj = 1; jj < 16; jj++) tm = fmaxf(tm, s[jj]);
            float nm = fmaxf(m, tm);
            float corr = ex2f(m - nm);
            m = nm;
            l *= corr;
            ull c2 = pack2(corr, corr);
#pragma unroll
            for (int u = 0; u < 8; u++) o2[u] = mul2(o2[u], c2);
#pragma unroll
            for (int jj = 0; jj < 16; jj++) {
                int j = c * 16 + jj;
                float p = ex2f(s[jj] - m);
                l += p;
                ull p2 = pack2(p, p);
                const ulonglong2* vr = (const ulonglong2*)&Vs[part][j * 16];
                ulonglong2 va = vr[0], vb = vr[1], vc = vr[2], vd = vr[3];
                ffma2(o2[0], p2, va.x);
                ffma2(o2[1], p2, va.y);
                ffma2(o2[2], p2, vb.x);
                ffma2(o2[3], p2, vb.y);
                ffma2(o2[4], p2, vc.x);
                ffma2(o2[5], p2, vc.y);
                ffma2(o2[6], p2, vd.x);
                ffma2(o2[7], p2, vd.y);
            }
        }
        __syncwarp();
    }

    if (part != 0) {
        float* d = &mrg[part - 1][lane][0];
        d[0] = m;
        d[1] = l;
#pragma unroll
        for (int u = 0; u < 8; u++) {
            float lo, hi;
            unpack2(o2[u], lo, hi);
            d[2 + 2 * u] = lo;
            d[3 + 2 * u] = hi;
        }
    }
    __syncthreads();
    if (part == 0) {
        float M = m;
#pragma unroll
        for (int p2i = 0; p2i < 3; p2i++) M = fmaxf(M, mrg[p2i][lane][0]);
        float c0 = ex2f(m - M);
        float L = l * c0;
        float o[16];
#pragma unroll
        for (int u = 0; u < 8; u++) {
            float lo, hi;
            unpack2(o2[u], lo, hi);
            o[2 * u] = lo * c0;
            o[2 * u + 1] = hi * c0;
        }
#pragma unroll
        for (int p2i = 0; p2i < 3; p2i++) {
            const float* sp = &mrg[p2i][lane][0];
            float cp = ex2f(sp[0] - M);
            L = fmaf(sp[1], cp, L);
#pragma unroll
            for (int c = 0; c < 16; c++) o[c] = fmaf(sp[2 + c], cp, o[c]);
        }
        float inv = 1.f / L;
#pragma unroll
        for (int c = 0; c < 16; c++) g_obuf[qi * 64 + hh * 16 + c] = o[c] * inv;
    }
}

// ---------------- out_proj + residual + LN + final linear --------------------
__global__ void __launch_bounds__(128) epi_kernel(
    const float* __restrict__ opw, const float* __restrict__ opb,
    const float* __restrict__ ang, const float* __restrict__ anb,
    const float* __restrict__ ow, const float* __restrict__ ob,
    float* __restrict__ out) {
    int tid = threadIdx.x;
    int d = tid & 63, g = tid >> 6;
    int n0 = blockIdx.x * 8;
    __shared__ __align__(16) float os[8 * 64];
    __shared__ __align__(16) float ts[8 * 64];
    __shared__ float ps[8][16], pq[8][16];
    __shared__ float mv[8][2];

    for (int i = tid; i < 8 * 64; i += 128) os[i] = g_obuf[n0 * 64 + i];
    float wr[64];
    {
        const float4* p4 = (const float4*)(opw + d * 64);
#pragma unroll
        for (int k = 0; k < 16; k++) {
            float4 f = p4[k];
            wr[4 * k] = f.x; wr[4 * k + 1] = f.y; wr[4 * k + 2] = f.z; wr[4 * k + 3] = f.w;
        }
    }
    float bb = opb[d];
    __syncthreads();
#pragma unroll
    for (int ni = 0; ni < 4; ni++) {
        int nn = g * 4 + ni;
        float acc = bb;
#pragma unroll
        for (int k = 0; k < 16; k++) {
            float4 h = *(const float4*)&os[nn * 64 + 4 * k];
            acc = fmaf(wr[4 * k], h.x, acc);
            acc = fmaf(wr[4 * k + 1], h.y, acc);
            acc = fmaf(wr[4 * k + 2], h.z, acc);
            acc = fmaf(wr[4 * k + 3], h.w, acc);
        }
        ts[nn * 64 + d] = g_agg[(n0 + nn) * 64 + d] + acc;
    }
    __syncthreads();
    {
        int n = tid >> 4, sg = tid & 15;
        float s = 0.f, qq = 0.f;
#pragma unroll
        for (int t = 0; t < 4; t++) {
            float v2 = ts[n * 64 + sg * 4 + t];
            s += v2; qq += v2 * v2;
        }
        ps[n][sg] = s; pq[n][sg] = qq;
    }
    __syncthreads();
    if (tid < 8) {
        float s = 0.f, qq = 0.f;
#pragma unroll
        for (int t = 0; t < 16; t++) { s += ps[tid][t]; qq += pq[tid][t]; }
        float mean = s * (1.f / 64.f);
        float var = qq * (1.f / 64.f) - mean * mean;
        mv[tid][0] = mean;
        mv[tid][1] = rsqrtf(var + 1e-5f);
    }
    __syncthreads();
    float gg = ang[d], gb = anb[d];
#pragma unroll
    for (int ni = 0; ni < 4; ni++) {
        int nn = g * 4 + ni;
        ts[nn * 64 + d] = (ts[nn * 64 + d] - mv[nn][0]) * mv[nn][1] * gg + gb;
    }
    {
        const float4* p4 = (const float4*)(ow + d * 64);
#pragma unroll
        for (int k = 0; k < 16; k++) {
            float4 f = p4[k];
            wr[4 * k] = f.x; wr[4 * k + 1] = f.y; wr[4 * k + 2] = f.z; wr[4 * k + 3] = f.w;
        }
    }
    float bo = ob[d];
    __syncthreads();
#pragma unroll
    for (int ni = 0; ni < 4; ni++) {
        int nn = g * 4 + ni;
        float acc = bo;
#pragma unroll
        for (int k = 0; k < 16; k++) {
            float4 h = *(const float4*)&ts[nn * 64 + 4 * k];
            acc = fmaf(wr[4 * k], h.x, acc);
            acc = fmaf(wr[4 * k + 1], h.y, acc);
            acc = fmaf(wr[4 * k + 2], h.z, acc);
            acc = fmaf(wr[4 * k + 3], h.w, acc);
        }
        out[(n0 + nn) * 64 + d] = acc;
    }
}

// ---------------- launch ----------------
extern "C" void kernel_launch(void* const* d_in, const int* in_sizes, int n_in,
                              void* d_out, int out_size) {
    const float* x        = (const float*)d_in[0];
    const float* eattr    = (const float*)d_in[1];
    const float* emb      = (const float*)d_in[2];
    const float* lin1_w   = (const float*)d_in[3];
    const float* lin1_b   = (const float*)d_in[4];
    const float* lay_w    = (const float*)d_in[5];
    const float* lay_b    = (const float*)d_in[6];
    const float* ln_g     = (const float*)d_in[7];
    const float* ln_b     = (const float*)d_in[8];
    const float* in_proj_w  = (const float*)d_in[9];
    const float* in_proj_b  = (const float*)d_in[10];
    const float* out_proj_w = (const float*)d_in[11];
    const float* out_proj_b = (const float*)d_in[12];
    const float* an_g     = (const float*)d_in[13];
    const float* an_b     = (const float*)d_in[14];
    const float* out_w    = (const float*)d_in[15];
    const float* out_b    = (const float*)d_in[16];
    const void*  ei       = d_in[17];
    const void*  ety      = d_in[18];

    int E = in_sizes[1];
    int N = in_sizes[0] / 6;

    cudaFuncSetAttribute(edge_kernel, cudaFuncAttributeMaxDynamicSharedMemorySize,
                         EDGE_DYN);

    detectAB_kernel<<<1, 64>>>((const unsigned*)ei, (const unsigned*)ety,
                               lay_w, ln_g, ln_b, lay_b);
    setup_kernel<<<N / 16 + 16 + N / 4, 256>>>(x, emb, lin1_w, lin1_b, ety,
                                               lay_w, ln_g, N);
    edge_kernel<<<(E + 127) / 128, 128, EDGE_DYN>>>(ei, eattr, lin1_w, ln_g,
                                                    ln_b, E);
    qkv_kernel<<<N / 32, 192>>>(in_proj_w, in_proj_b, N);
    attn_kernel<<<dim3(N / 32, 4), 128>>>(N);
    epi_kernel<<<N / 8, 128>>>(out_proj_w, out_proj_b, an_g, an_b, out_w, out_b,
                               (float*)d_out);
}

// round 12
// speedup vs baseline: 1.0581x; 1.0581x over previous
#include <cuda_runtime.h>
#include <cstdint>

#define NMAX 4096
#define HID 64

typedef unsigned long long ull;

// ---------------- device scratch ----------------
__device__ __align__(256) float g_P[NMAX * HID];
__device__ __align__(256) float g_agg[NMAX * HID];
__device__ __align__(256) float g_q[4 * NMAX * 16];
__device__ __align__(256) float g_k[4 * NMAX * 16];
__device__ __align__(256) float g_v[4 * NMAX * 16];
__device__ __align__(256) float g_obuf[NMAX * HID];
__device__ __align__(256) float g_wgk[64 * 64];  // [k][d] = w2[d][k]*g[k] (scalar)
__device__ __align__(256) float g_A[64];         // A[d] = sum_k w2[d][k]*g[k]
__device__ __align__(256) float g_Bc[64];        // B[d] + b2[d]
__device__ int g_is64_ei;
__device__ int g_is64_ty;

__device__ __forceinline__ long ldidx(const void* p, long i, int is64) {
    return is64 ? (long)((const long long*)p)[i] : (long)((const int*)p)[i];
}

// ---------------- packed f32x2 helpers ----------------
__device__ __forceinline__ ull pack2(float lo, float hi) {
    ull r; asm("mov.b64 %0, {%1, %2};" : "=l"(r) : "f"(lo), "f"(hi)); return r;
}
__device__ __forceinline__ void unpack2(ull v, float& lo, float& hi) {
    asm("mov.b64 {%0, %1}, %2;" : "=f"(lo), "=f"(hi) : "l"(v));
}
__device__ __forceinline__ void ffma2(ull& d, ull a, ull b) {
    asm("fma.rn.f32x2 %0, %1, %2, %0;" : "+l"(d) : "l"(a), "l"(b));
}
__device__ __forceinline__ ull mul2(ull a, ull b) {
    ull r; asm("mul.rn.f32x2 %0, %1, %2;" : "=l"(r) : "l"(a), "l"(b)); return r;
}
__device__ __forceinline__ float ex2f(float x) {
    float r; asm("ex2.approx.ftz.f32 %0, %1;" : "=f"(r) : "f"(x)); return r;
}

// ---------------- detect dtypes + per-dim LN1-fold constants ----------------
__global__ void detectAB_kernel(const unsigned* ei, const unsigned* ty,
                                const float* __restrict__ w2g,
                                const float* __restrict__ lng,
                                const float* __restrict__ lnb,
                                const float* __restrict__ b2) {
    int d = threadIdx.x;   // 64
    float A = 0.f, B = 0.f;
#pragma unroll 8
    for (int k = 0; k < 64; k++) {
        float w = w2g[d * 64 + k];
        A = fmaf(w, lng[k], A);
        B = fmaf(w, lnb[k], B);
    }
    g_A[d] = A;
    g_Bc[d] = B + b2[d];
    if (d == 0) {
        unsigned a = 0;
        for (int i = 0; i < 32; i++) a |= ei[2 * i + 1];
        g_is64_ei = (a == 0) ? 1 : 0;
        unsigned b = 0;
        for (int i = 0; i < 32; i++) b |= ty[2 * i + 1];
        g_is64_ty = (b == 0) ? 1 : 0;
    }
}

// ---------------- fused setup: zero g_agg | pack w*g k-major | prep P -------
__global__ void __launch_bounds__(256) setup_kernel(
    const float* __restrict__ x, const float* __restrict__ emb,
    const float* __restrict__ w1, const float* __restrict__ b1,
    const void* __restrict__ ety, const float* __restrict__ w2g,
    const float* __restrict__ lng, int N) {
    int bid = blockIdx.x, t = threadIdx.x;
    int zb = N / 16;
    if (bid < zb) {
        ((float4*)g_agg)[bid * 256 + t] = make_float4(0.f, 0.f, 0.f, 0.f);
    } else if (bid < zb + 16) {
        int i = (bid - zb) * 256 + t;        // i = k*64 + d
        int k = i >> 6, d = i & 63;
        g_wgk[i] = w2g[d * 64 + k] * lng[k];
    } else {
        int nb = bid - zb - 16;
        int grp = t >> 6, d = t & 63;
        int n = nb * 4 + grp;
        __shared__ float xs[4][16];
        int is64 = g_is64_ty;
        if (d < 6) {
            xs[grp][d] = x[n * 6 + d];
        } else if (d < 14) {
            long tt = ldidx(ety, n, is64);
            xs[grp][d] = emb[tt * 8 + (d - 6)];
        }
        __syncthreads();
        float acc = b1[d];
#pragma unroll
        for (int k = 0; k < 14; k++) acc = fmaf(xs[grp][k], w1[d * 15 + k], acc);
        g_P[n * HID + d] = acc;
    }
}

// ---------------- edge MLP + scatter-add ------------------------------------
// 128 threads / 128 edges. Stage B: warp = 16-dim group; broadcast weight
// pairs, h duplicated in-reg. Stage C: two-pass; pass2 stages LN2 rows in
// smem [e][65], then COALESCED cooperative red (16 lanes = one edge row ->
// 4 lines per warp-RED instead of 32).
#define EDGE_DYN (32768 + 16384)
__global__ void __launch_bounds__(128, 4) edge_kernel(
    const void* __restrict__ ei, const float* __restrict__ eattr,
    const float* __restrict__ w1, const float* __restrict__ lng,
    const float* __restrict__ lnb, int nE) {
    extern __shared__ __align__(16) char dyn[];
    float* h1f = (float*)dyn;                 // 32KB [k][128]; overlaid later
    float* w2s = (float*)(dyn + 32768);       // 16KB [k][64] scalar w*g
    __shared__ __align__(16) float w1ls[64];
    __shared__ __align__(16) float As[64];
    __shared__ __align__(16) float Bcs[64];
    __shared__ __align__(16) float gs[64];
    __shared__ __align__(16) float bs[64];
    __shared__ __align__(8) float rst[128 * 2];
    __shared__ int sdst[128];

    int tid = threadIdx.x;
    {   // stage scalar weights: 1024 float4 over 128 threads
        const float4* wsrc = (const float4*)g_wgk;
        float4* wdst = (float4*)w2s;
#pragma unroll
        for (int i = 0; i < 8; i++) wdst[i * 128 + tid] = wsrc[i * 128 + tid];
    }
    if (tid < 64) {
        w1ls[tid] = w1[tid * 15 + 14];
        As[tid] = g_A[tid];
        Bcs[tid] = g_Bc[tid];
        gs[tid] = lng[tid];
        bs[tid] = lnb[tid];
    }
    long e = (long)blockIdx.x * 128 + tid;
    bool act = e < nE;
    int is64 = g_is64_ei;
    long src = 0;
    float a = 0.f;
    {
        long dl = -1;
        if (act) {
            src = ldidx(ei, e, is64);
            dl = ldidx(ei, (long)nE + e, is64);
            a = eattr[e];
        }
        sdst[tid] = (int)dl;
    }
    __syncthreads();

    // ---- Stage A: x = relu(P[src] + a*w1_last); stats; raw x -> smem ----
    {
        const float4* pr = (const float4*)(g_P + src * 64);
        float s1 = 0.f, q1 = 0.f;
#pragma unroll
        for (int g = 0; g < 16; g++) {
            float4 p = pr[g];
            float4 wl = ((const float4*)w1ls)[g];
            float x0 = fmaxf(fmaf(a, wl.x, p.x), 0.f);
            float x1 = fmaxf(fmaf(a, wl.y, p.y), 0.f);
            float x2 = fmaxf(fmaf(a, wl.z, p.z), 0.f);
            float x3 = fmaxf(fmaf(a, wl.w, p.w), 0.f);
            h1f[(4 * g + 0) * 128 + tid] = x0;
            h1f[(4 * g + 1) * 128 + tid] = x1;
            h1f[(4 * g + 2) * 128 + tid] = x2;
            h1f[(4 * g + 3) * 128 + tid] = x3;
            s1 += (x0 + x1) + (x2 + x3);
            q1 = fmaf(x0, x0, q1); q1 = fmaf(x1, x1, q1);
            q1 = fmaf(x2, x2, q1); q1 = fmaf(x3, x3, q1);
        }
        float mean1 = s1 * (1.f / 64.f);
        float var1 = fmaf(-mean1, mean1, q1 * (1.f / 64.f));
        float r1 = rsqrtf(var1 + 1e-5f);
        rst[2 * tid] = r1;
        rst[2 * tid + 1] = -mean1 * r1;
    }
    __syncthreads();

    // ---- Stage B: acc over dim-pairs; w pairs native, h duplicated ----
    int lane = tid & 31, wrp = tid >> 5;
    ull acc[4][8];   // [edge 0..3][dim-pair 0..7], dims = wrp*16 + 2*jp (+1)
#pragma unroll
    for (int ee = 0; ee < 4; ee++)
#pragma unroll
        for (int jp = 0; jp < 8; jp++) acc[ee][jp] = 0ull;
    {
        const float4* hb4 = (const float4*)h1f;
        const float* wbase = w2s + wrp * 16;
#pragma unroll 8
        for (int k = 0; k < 64; k++) {
            float4 hv = hb4[k * 32 + lane];        // edges 4*lane..+3, coalesced
            ull h0 = pack2(hv.x, hv.x);
            ull h1 = pack2(hv.y, hv.y);
            ull h2 = pack2(hv.z, hv.z);
            ull h3 = pack2(hv.w, hv.w);
            const ulonglong2* wk = (const ulonglong2*)(wbase + k * 64);
            ulonglong2 wA = wk[0];
            ulonglong2 wB = wk[1];
            ulonglong2 wC = wk[2];
            ulonglong2 wD = wk[3];
            ffma2(acc[0][0], wA.x, h0); ffma2(acc[1][0], wA.x, h1);
            ffma2(acc[2][0], wA.x, h2); ffma2(acc[3][0], wA.x, h3);
            ffma2(acc[0][1], wA.y, h0); ffma2(acc[1][1], wA.y, h1);
            ffma2(acc[2][1], wA.y, h2); ffma2(acc[3][1], wA.y, h3);
            ffma2(acc[0][2], wB.x, h0); ffma2(acc[1][2], wB.x, h1);
            ffma2(acc[2][2], wB.x, h2); ffma2(acc[3][2], wB.x, h3);
            ffma2(acc[0][3], wB.y, h0); ffma2(acc[1][3], wB.y, h1);
            ffma2(acc[2][3], wB.y, h2); ffma2(acc[3][3], wB.y, h3);
            ffma2(acc[0][4], wC.x, h0); ffma2(acc[1][4], wC.x, h1);
            ffma2(acc[2][4], wC.x, h2); ffma2(acc[3][4], wC.x, h3);
            ffma2(acc[0][5], wC.y, h0); ffma2(acc[1][5], wC.y, h1);
            ffma2(acc[2][5], wC.y, h2); ffma2(acc[3][5], wC.y, h3);
            ffma2(acc[0][6], wD.x, h0); ffma2(acc[1][6], wD.x, h1);
            ffma2(acc[2][6], wD.x, h2); ffma2(acc[3][6], wD.x, h3);
            ffma2(acc[0][7], wD.y, h0); ffma2(acc[1][7], wD.y, h1);
            ffma2(acc[2][7], wD.y, h2); ffma2(acc[3][7], wD.y, h3);
        }
    }

    // ---- Stage C (two-pass) ----
    float Ar[16], Br[16];
    {
        const float4* ap = (const float4*)(As + wrp * 16);
        const float4* bp = (const float4*)(Bcs + wrp * 16);
#pragma unroll
        for (int u = 0; u < 4; u++) {
            float4 av = ap[u], bv = bp[u];
            Ar[4 * u] = av.x; Ar[4 * u + 1] = av.y; Ar[4 * u + 2] = av.z; Ar[4 * u + 3] = av.w;
            Br[4 * u] = bv.x; Br[4 * u + 1] = bv.y; Br[4 * u + 2] = bv.z; Br[4 * u + 3] = bv.w;
        }
    }
    float rr[4], mm[4];
#pragma unroll
    for (int i = 0; i < 4; i++) {
        rr[i] = rst[2 * (4 * lane + i)];
        mm[i] = rst[2 * (4 * lane + i) + 1];
    }
    // pass 1: stats only (v recomputed from packed acc, not stored)
    float se[4] = {0.f, 0.f, 0.f, 0.f}, qe[4] = {0.f, 0.f, 0.f, 0.f};
#pragma unroll
    for (int ee = 0; ee < 4; ee++) {
#pragma unroll
        for (int jp = 0; jp < 8; jp++) {
            float lo, hi;
            unpack2(acc[ee][jp], lo, hi);
            int j0 = 2 * jp, j1 = 2 * jp + 1;
            float v0 = fmaxf(fmaf(rr[ee], lo, fmaf(mm[ee], Ar[j0], Br[j0])), 0.f);
            float v1 = fmaxf(fmaf(rr[ee], hi, fmaf(mm[ee], Ar[j1], Br[j1])), 0.f);
            se[ee] += v0 + v1;
            qe[ee] = fmaf(v0, v0, qe[ee]);
            qe[ee] = fmaf(v1, v1, qe[ee]);
        }
    }
    __syncthreads();   // h1f reads done; overlay partials
    float* ps = h1f;            // [4][128]
    float* pq = h1f + 512;      // [4][128]
#pragma unroll
    for (int i = 0; i < 4; i++) {
        ps[wrp * 128 + 4 * lane + i] = se[i];
        pq[wrp * 128 + 4 * lane + i] = qe[i];
    }
    __syncthreads();
    {
        float s = ps[tid] + ps[128 + tid] + ps[256 + tid] + ps[384 + tid];
        float q = pq[tid] + pq[128 + tid] + pq[256 + tid] + pq[384 + tid];
        float mean = s * (1.f / 64.f);
        float var = fmaf(-mean, mean, q * (1.f / 64.f));
        float r = rsqrtf(var + 1e-5f);
        rst[2 * tid] = r;
        rst[2 * tid + 1] = -mean * r;
    }
    __syncthreads();
    // pass 2: LN2 apply into smem rows out[e][65] (overlays dyn; partials dead)
    float* outb = (float*)dyn;
#pragma unroll
    for (int ee = 0; ee < 4; ee++) {
        int eIdx = 4 * lane + ee;
        float r2 = rst[2 * eIdx];
        float mr2 = rst[2 * eIdx + 1];
        float* orow = outb + eIdx * 65 + wrp * 16;
#pragma unroll
        for (int u = 0; u < 4; u++) {
            int jpA = 2 * u, jpB = 2 * u + 1;
            float lo0, hi0, lo1, hi1;
            unpack2(acc[ee][jpA], lo0, hi0);
            unpack2(acc[ee][jpB], lo1, hi1);
            int j0 = 4 * u, j1 = j0 + 1, j2 = j0 + 2, j3 = j0 + 3;
            float v0 = fmaxf(fmaf(rr[ee], lo0, fmaf(mm[ee], Ar[j0], Br[j0])), 0.f);
            float v1 = fmaxf(fmaf(rr[ee], hi0, fmaf(mm[ee], Ar[j1], Br[j1])), 0.f);
            float v2 = fmaxf(fmaf(rr[ee], lo1, fmaf(mm[ee], Ar[j2], Br[j2])), 0.f);
            float v3 = fmaxf(fmaf(rr[ee], hi1, fmaf(mm[ee], Ar[j3], Br[j3])), 0.f);
            float4 gv = ((const float4*)(gs + wrp * 16))[u];
            float4 bv = ((const float4*)(bs + wrp * 16))[u];
            orow[4 * u + 0] = fmaf(fmaf(v0, r2, mr2), gv.x, bv.x);
            orow[4 * u + 1] = fmaf(fmaf(v1, r2, mr2), gv.y, bv.y);
            orow[4 * u + 2] = fmaf(fmaf(v2, r2, mr2), gv.z, bv.z);
            orow[4 * u + 3] = fmaf(fmaf(v3, r2, mr2), gv.w, bv.w);
        }
    }
    __syncthreads();
    // coalesced cooperative red: 16 lanes cover one edge's full row
    {
        int ce = tid >> 4;   // edge-slot within iteration (0..7)
        int cc = tid & 15;   // 4-float chunk (0..15)
#pragma unroll
        for (int i = 0; i < 16; i++) {
            int eIdx = i * 8 + ce;
            int dnL = sdst[eIdx];
            const float* orow = outb + eIdx * 65 + 4 * cc;
            float o0 = orow[0], o1 = orow[1], o2 = orow[2], o3 = orow[3];
            if (dnL >= 0) {
                float* p = g_agg + (long)dnL * 64 + 4 * cc;
                asm volatile("red.global.add.v4.f32 [%0], {%1,%2,%3,%4};"
                             :: "l"(p), "f"(o0), "f"(o1), "f"(o2), "f"(o3)
                             : "memory");
            }
        }
    }
}

// ---------------- qkv = h @ in_proj_w.T + b, 32 nodes/block ------------------
__global__ void __launch_bounds__(192) qkv_kernel(const float* __restrict__ w,
                                                  const float* __restrict__ b, int N) {
    __shared__ __align__(16) float hs[32 * 64];
    int tid = threadIdx.x;
    int n0 = blockIdx.x * 32;
    for (int i = tid; i < 32 * 64 / 4; i += 192)
        ((float4*)hs)[i] = ((const float4*)(g_agg + n0 * 64))[i];
    float wr[64];
    {
        const float4* p4 = (const float4*)(w + tid * 64);
#pragma unroll
        for (int k = 0; k < 16; k++) {
            float4 f = p4[k];
            wr[4 * k] = f.x; wr[4 * k + 1] = f.y; wr[4 * k + 2] = f.z; wr[4 * k + 3] = f.w;
        }
    }
    float br = b[tid];
    __syncthreads();
    int sec = tid / 64, wi = tid % 64, hh = wi / 16, dd = wi % 16;
    float* dst = sec == 0 ? g_q : (sec == 1 ? g_k : g_v);
#pragma unroll 4
    for (int nn = 0; nn < 32; nn++) {
        float acc = br;
#pragma unroll
        for (int k = 0; k < 16; k++) {
            float4 h = *(const float4*)&hs[nn * 64 + 4 * k];
            acc = fmaf(wr[4 * k], h.x, acc);
            acc = fmaf(wr[4 * k + 1], h.y, acc);
            acc = fmaf(wr[4 * k + 2], h.z, acc);
            acc = fmaf(wr[4 * k + 3], h.w, acc);
        }
        dst[hh * N * 16 + (n0 + nn) * 16 + dd] = acc;
    }
}

// ---------------- flash attention, f32x2, log2-domain softmax ---------------
__global__ void __launch_bounds__(128) attn_kernel(int N) {
    int hh = blockIdx.y;
    int part = threadIdx.x >> 5;
    int lane = threadIdx.x & 31;
    int qi = blockIdx.x * 32 + lane;
    const float* Q = g_q + hh * N * 16;
    const float* K = g_k + hh * N * 16;
    const float* V = g_v + hh * N * 16;

    __shared__ __align__(16) float Ks[4][64 * 16];
    __shared__ __align__(16) float Vs[4][64 * 16];
    __shared__ float mrg[3][32][18];

    // scale = (1/4) * log2(e): scores in log2 domain; softmax ratio unchanged.
    const float QS = 0.25f * 1.4426950408889634f;
    ull q2[8];
    {
        const float4* qp = (const float4*)(Q + qi * 16);
#pragma unroll
        for (int u = 0; u < 4; u++) {
            float4 f = qp[u];
            q2[2 * u] = pack2(f.x * QS, f.y * QS);
            q2[2 * u + 1] = pack2(f.z * QS, f.w * QS);
        }
    }
    ull o2[8];
#pragma unroll
    for (int u = 0; u < 8; u++) o2[u] = 0ull;
    float m = -1e30f, l = 0.f;

    int j0 = part * (N >> 2);
    for (int kt = 0; kt < (N >> 2); kt += 64) {
        {
            const float4* ksrc = (const float4*)(K + (j0 + kt) * 16);
            const float4* vsrc = (const float4*)(V + (j0 + kt) * 16);
            float4* kdst = (float4*)Ks[part];
            float4* vdst = (float4*)Vs[part];
#pragma unroll
            for (int u = 0; u < 8; u++) {
                kdst[u * 32 + lane] = ksrc[u * 32 + lane];
                vdst[u * 32 + lane] = vsrc[u * 32 + lane];
            }
        }
        __syncwarp();
        for (int c = 0; c < 4; c++) {
            float s[16];
#pragma unroll
            for (int jj = 0; jj < 16; jj++) {
                int j = c * 16 + jj;
                const ulonglong2* kr = (const ulonglong2*)&Ks[part][j * 16];
                ulonglong2 ka = kr[0], kb = kr[1], kc = kr[2], kd = kr[3];
                ull s2 = mul2(q2[0], ka.x);
                ffma2(s2, q2[1], ka.y);
                ffma2(s2, q2[2], kb.x);
                ffma2(s2, q2[3], kb.y);
                ffma2(s2, q2[4], kc.x);
                ffma2(s2, q2[5], kc.y);
                ffma2(s2, q2[6], kd.x);
                ffma2(s2, q2[7], kd.y);
                float slo, shi;
                unpack2(s2, slo, shi);
                s[jj] = slo + shi;
            }
            float tm = s[0];
#pragma unroll
            for (int jj = 1; jj < 16; jj++) tm = fmaxf(tm, s[jj]);
            float nm = fmaxf(m, tm);
            float corr = ex2f(m - nm);
            m = nm;
            l *= corr;
            ull c2 = pack2(corr, corr);
#pragma unroll
            for (int u = 0; u < 8; u++) o2[u] = mul2(o2[u], c2);
#pragma unroll
            for (int jj = 0; jj < 16; jj++) {
                int j = c * 16 + jj;
                float p = ex2f(s[jj] - m);
                l += p;
                ull p2 = pack2(p, p);
                const ulonglong2* vr = (const ulonglong2*)&Vs[part][j * 16];
                ulonglong2 va = vr[0], vb = vr[1], vc = vr[2], vd = vr[3];
                ffma2(o2[0], p2, va.x);
                ffma2(o2[1], p2, va.y);
                ffma2(o2[2], p2, vb.x);
                ffma2(o2[3], p2, vb.y);
                ffma2(o2[4], p2, vc.x);
                ffma2(o2[5], p2, vc.y);
                ffma2(o2[6], p2, vd.x);
                ffma2(o2[7], p2, vd.y);
            }
        }
        __syncwarp();
    }

    if (part != 0) {
        float* d = &mrg[part - 1][lane][0];
        d[0] = m;
        d[1] = l;
#pragma unroll
        for (int u = 0; u < 8; u++) {
            float lo, hi;
            unpack2(o2[u], lo, hi);
            d[2 + 2 * u] = lo;
            d[3 + 2 * u] = hi;
        }
    }
    __syncthreads();
    if (part == 0) {
        float M = m;
#pragma unroll
        for (int p2i = 0; p2i < 3; p2i++) M = fmaxf(M, mrg[p2i][lane][0]);
        float c0 = ex2f(m - M);
        float L = l * c0;
        float o[16];
#pragma unroll
        for (int u = 0; u < 8; u++) {
            float lo, hi;
            unpack2(o2[u], lo, hi);
            o[2 * u] = lo * c0;
            o[2 * u + 1] = hi * c0;
        }
#pragma unroll
        for (int p2i = 0; p2i < 3; p2i++) {
            const float* sp = &mrg[p2i][lane][0];
            float cp = ex2f(sp[0] - M);
            L = fmaf(sp[1], cp, L);
#pragma unroll
            for (int c = 0; c < 16; c++) o[c] = fmaf(sp[2 + c], cp, o[c]);
        }
        float inv = 1.f / L;
#pragma unroll
        for (int c = 0; c < 16; c++) g_obuf[qi * 64 + hh * 16 + c] = o[c] * inv;
    }
}

// ---------------- out_proj + residual + LN + final linear --------------------
__global__ void __launch_bounds__(128) epi_kernel(
    const float* __restrict__ opw, const float* __restrict__ opb,
    const float* __restrict__ ang, const float* __restrict__ anb,
    const float* __restrict__ ow, const float* __restrict__ ob,
    float* __restrict__ out) {
    int tid = threadIdx.x;
    int d = tid & 63, g = tid >> 6;
    int n0 = blockIdx.x * 8;
    __shared__ __align__(16) float os[8 * 64];
    __shared__ __align__(16) float ts[8 * 64];
    __shared__ float ps[8][16], pq[8][16];
    __shared__ float mv[8][2];

    for (int i = tid; i < 8 * 64; i += 128) os[i] = g_obuf[n0 * 64 + i];
    float wr[64];
    {
        const float4* p4 = (const float4*)(opw + d * 64);
#pragma unroll
        for (int k = 0; k < 16; k++) {
            float4 f = p4[k];
            wr[4 * k] = f.x; wr[4 * k + 1] = f.y; wr[4 * k + 2] = f.z; wr[4 * k + 3] = f.w;
        }
    }
    float bb = opb[d];
    __syncthreads();
#pragma unroll
    for (int ni = 0; ni < 4; ni++) {
        int nn = g * 4 + ni;
        float acc = bb;
#pragma unroll
        for (int k = 0; k < 16; k++) {
            float4 h = *(const float4*)&os[nn * 64 + 4 * k];
            acc = fmaf(wr[4 * k], h.x, acc);
            acc = fmaf(wr[4 * k + 1], h.y, acc);
            acc = fmaf(wr[4 * k + 2], h.z, acc);
            acc = fmaf(wr[4 * k + 3], h.w, acc);
        }
        ts[nn * 64 + d] = g_agg[(n0 + nn) * 64 + d] + acc;
    }
    __syncthreads();
    {
        int n = tid >> 4, sg = tid & 15;
        float s = 0.f, qq = 0.f;
#pragma unroll
        for (int t = 0; t < 4; t++) {
            float v2 = ts[n * 64 + sg * 4 + t];
            s += v2; qq += v2 * v2;
        }
        ps[n][sg] = s; pq[n][sg] = qq;
    }
    __syncthreads();
    if (tid < 8) {
        float s = 0.f, qq = 0.f;
#pragma unroll
        for (int t = 0; t < 16; t++) { s += ps[tid][t]; qq += pq[tid][t]; }
        float mean = s * (1.f / 64.f);
        float var = qq * (1.f / 64.f) - mean * mean;
        mv[tid][0] = mean;
        mv[tid][1] = rsqrtf(var + 1e-5f);
    }
    __syncthreads();
    float gg = ang[d], gb = anb[d];
#pragma unroll
    for (int ni = 0; ni < 4; ni++) {
        int nn = g * 4 + ni;
        ts[nn * 64 + d] = (ts[nn * 64 + d] - mv[nn][0]) * mv[nn][1] * gg + gb;
    }
    {
        const float4* p4 = (const float4*)(ow + d * 64);
#pragma unroll
        for (int k = 0; k < 16; k++) {
            float4 f = p4[k];
            wr[4 * k] = f.x; wr[4 * k + 1] = f.y; wr[4 * k + 2] = f.z; wr[4 * k + 3] = f.w;
        }
    }
    float bo = ob[d];
    __syncthreads();
#pragma unroll
    for (int ni = 0; ni < 4; ni++) {
        int nn = g * 4 + ni;
        float acc = bo;
#pragma unroll
        for (int k = 0; k < 16; k++) {
            float4 h = *(const float4*)&ts[nn * 64 + 4 * k];
            acc = fmaf(wr[4 * k], h.x, acc);
            acc = fmaf(wr[4 * k + 1], h.y, acc);
            acc = fmaf(wr[4 * k + 2], h.z, acc);
            acc = fmaf(wr[4 * k + 3], h.w, acc);
        }
        out[(n0 + nn) * 64 + d] = acc;
    }
}

// ---------------- launch ----------------
extern "C" void kernel_launch(void* const* d_in, const int* in_sizes, int n_in,
                              void* d_out, int out_size) {
    const float* x        = (const float*)d_in[0];
    const float* eattr    = (const float*)d_in[1];
    const float* emb      = (const float*)d_in[2];
    const float* lin1_w   = (const float*)d_in[3];
    const float* lin1_b   = (const float*)d_in[4];
    const float* lay_w    = (const float*)d_in[5];
    const float* lay_b    = (const float*)d_in[6];
    const float* ln_g     = (const float*)d_in[7];
    const float* ln_b     = (const float*)d_in[8];
    const float* in_proj_w  = (const float*)d_in[9];
    const float* in_proj_b  = (const float*)d_in[10];
    const float* out_proj_w = (const float*)d_in[11];
    const float* out_proj_b = (const float*)d_in[12];
    const float* an_g     = (const float*)d_in[13];
    const float* an_b     = (const float*)d_in[14];
    const float* out_w    = (const float*)d_in[15];
    const float* out_b    = (const float*)d_in[16];
    const void*  ei       = d_in[17];
    const void*  ety      = d_in[18];

    int E = in_sizes[1];
    int N = in_sizes[0] / 6;

    cudaFuncSetAttribute(edge_kernel, cudaFuncAttributeMaxDynamicSharedMemorySize,
                         EDGE_DYN);

    detectAB_kernel<<<1, 64>>>((const unsigned*)ei, (const unsigned*)ety,
                               lay_w, ln_g, ln_b, lay_b);
    setup_kernel<<<N / 16 + 16 + N / 4, 256>>>(x, emb, lin1_w, lin1_b, ety,
                                               lay_w, ln_g, N);
    edge_kernel<<<(E + 127) / 128, 128, EDGE_DYN>>>(ei, eattr, lin1_w, ln_g,
                                                    ln_b, E);
    qkv_kernel<<<N / 32, 192>>>(in_proj_w, in_proj_b, N);
    attn_kernel<<<dim3(N / 32, 4), 128>>>(N);
    epi_kernel<<<N / 8, 128>>>(out_proj_w, out_proj_b, an_g, an_b, out_w, out_b,
                               (float*)d_out);
}

// round 13
// speedup vs baseline: 1.0586x; 1.0004x over previous
#include <cuda_runtime.h>
#include <cstdint>

#define NMAX 4096
#define HID 64

typedef unsigned long long ull;

// ---------------- device scratch ----------------
__device__ __align__(256) float g_P[NMAX * HID];
__device__ __align__(256) float g_agg[NMAX * HID];
__device__ __align__(256) float g_q[4 * NMAX * 16];
__device__ __align__(256) float g_k[4 * NMAX * 16];
__device__ __align__(256) float g_v[4 * NMAX * 16];
__device__ __align__(256) float g_obuf[NMAX * HID];
__device__ __align__(256) float g_wgk[64 * 64];  // [k][d] = w2[d][k]*g[k] (scalar)
__device__ __align__(256) float g_A[64];         // A[d] = sum_k w2[d][k]*g[k]
__device__ __align__(256) float g_Bc[64];        // B[d] + b2[d]
__device__ int g_is64_ei;
__device__ int g_is64_ty;

__device__ __forceinline__ long ldidx(const void* p, long i, int is64) {
    return is64 ? (long)((const long long*)p)[i] : (long)((const int*)p)[i];
}

// ---------------- packed f32x2 helpers ----------------
__device__ __forceinline__ ull pack2(float lo, float hi) {
    ull r; asm("mov.b64 %0, {%1, %2};" : "=l"(r) : "f"(lo), "f"(hi)); return r;
}
__device__ __forceinline__ void unpack2(ull v, float& lo, float& hi) {
    asm("mov.b64 {%0, %1}, %2;" : "=f"(lo), "=f"(hi) : "l"(v));
}
__device__ __forceinline__ void ffma2(ull& d, ull a, ull b) {
    asm("fma.rn.f32x2 %0, %1, %2, %0;" : "+l"(d) : "l"(a), "l"(b));
}
__device__ __forceinline__ ull mul2(ull a, ull b) {
    ull r; asm("mul.rn.f32x2 %0, %1, %2;" : "=l"(r) : "l"(a), "l"(b)); return r;
}
__device__ __forceinline__ float ex2f(float x) {
    float r; asm("ex2.approx.ftz.f32 %0, %1;" : "=f"(r) : "f"(x)); return r;
}

// ---------------- detect dtypes + per-dim LN1-fold constants ----------------
__global__ void detectAB_kernel(const unsigned* ei, const unsigned* ty,
                                const float* __restrict__ w2g,
                                const float* __restrict__ lng,
                                const float* __restrict__ lnb,
                                const float* __restrict__ b2) {
    int d = threadIdx.x;   // 64
    float A = 0.f, B = 0.f;
#pragma unroll 8
    for (int k = 0; k < 64; k++) {
        float w = w2g[d * 64 + k];
        A = fmaf(w, lng[k], A);
        B = fmaf(w, lnb[k], B);
    }
    g_A[d] = A;
    g_Bc[d] = B + b2[d];
    if (d == 0) {
        unsigned a = 0;
        for (int i = 0; i < 32; i++) a |= ei[2 * i + 1];
        g_is64_ei = (a == 0) ? 1 : 0;
        unsigned b = 0;
        for (int i = 0; i < 32; i++) b |= ty[2 * i + 1];
        g_is64_ty = (b == 0) ? 1 : 0;
    }
}

// ---------------- fused setup: zero g_agg | pack w*g k-major | prep P -------
__global__ void __launch_bounds__(256) setup_kernel(
    const float* __restrict__ x, const float* __restrict__ emb,
    const float* __restrict__ w1, const float* __restrict__ b1,
    const void* __restrict__ ety, const float* __restrict__ w2g,
    const float* __restrict__ lng, int N) {
    int bid = blockIdx.x, t = threadIdx.x;
    int zb = N / 16;
    if (bid < zb) {
        ((float4*)g_agg)[bid * 256 + t] = make_float4(0.f, 0.f, 0.f, 0.f);
    } else if (bid < zb + 16) {
        int i = (bid - zb) * 256 + t;        // i = k*64 + d
        int k = i >> 6, d = i & 63;
        g_wgk[i] = w2g[d * 64 + k] * lng[k];
    } else {
        int nb = bid - zb - 16;
        int grp = t >> 6, d = t & 63;
        int n = nb * 4 + grp;
        __shared__ float xs[4][16];
        int is64 = g_is64_ty;
        if (d < 6) {
            xs[grp][d] = x[n * 6 + d];
        } else if (d < 14) {
            long tt = ldidx(ety, n, is64);
            xs[grp][d] = emb[tt * 8 + (d - 6)];
        }
        __syncthreads();
        float acc = b1[d];
#pragma unroll
        for (int k = 0; k < 14; k++) acc = fmaf(xs[grp][k], w1[d * 15 + k], acc);
        g_P[n * HID + d] = acc;
    }
}

// ---------------- edge MLP + scatter-add ------------------------------------
// 128 threads / 128 edges. Stage A: COALESCED cooperative gather (16 lanes =
// one edge row -> 4 lines/warp-LDG), rotated-swizzle k-major store, stats via
// smem partials. Stage B: broadcast weight pairs, h duplicated, swizzled read.
// Stage C: two-pass + coalesced cooperative red (R12).
#define EDGE_DYN 49280
__global__ void __launch_bounds__(128, 4) edge_kernel(
    const void* __restrict__ ei, const float* __restrict__ eattr,
    const float* __restrict__ w1, const float* __restrict__ lng,
    const float* __restrict__ lnb, int nE) {
    extern __shared__ __align__(16) char dyn[];
    float* h1f = (float*)dyn;                 // 32KB swizzled [k][128]
    float* w2s = (float*)(dyn + 32768);       // 16KB [k][64] (after stage A)
    float* ps2 = (float*)(dyn + 32768);       // stage A: partial s [cc*129+e]
    float* qs2 = ps2 + 2064;                  // stage A: partial q
    __shared__ __align__(16) float w1ls[64];
    __shared__ __align__(16) float As[64];
    __shared__ __align__(16) float Bcs[64];
    __shared__ __align__(16) float gs[64];
    __shared__ __align__(16) float bs[64];
    __shared__ __align__(8) float rst[128 * 2];
    __shared__ int sdst[128];
    __shared__ int ssrc[128];
    __shared__ float sat[128];

    int tid = threadIdx.x;
    if (tid < 64) {
        w1ls[tid] = w1[tid * 15 + 14];
        As[tid] = g_A[tid];
        Bcs[tid] = g_Bc[tid];
        gs[tid] = lng[tid];
        bs[tid] = lnb[tid];
    }
    long e = (long)blockIdx.x * 128 + tid;
    bool act = e < nE;
    int is64 = g_is64_ei;
    {
        long dl = -1, srcl = 0;
        float a = 0.f;
        if (act) {
            srcl = ldidx(ei, e, is64);
            dl = ldidx(ei, (long)nE + e, is64);
            a = eattr[e];
        }
        ssrc[tid] = (int)srcl;
        sdst[tid] = (int)dl;
        sat[tid] = a;
    }
    __syncthreads();

    // ---- Stage A: coalesced gather; relu; swizzled k-major store; partials -
    {
        int ce = tid >> 4, cc = tid & 15;
        float4 wl = ((const float4*)w1ls)[cc];
#pragma unroll
        for (int i = 0; i < 16; i++) {
            int eIdx = i * 8 + ce;
            float4 p = ((const float4*)(g_P + (long)ssrc[eIdx] * 64))[cc];
            float a = sat[eIdx];
            float x0 = fmaxf(fmaf(a, wl.x, p.x), 0.f);
            float x1 = fmaxf(fmaf(a, wl.y, p.y), 0.f);
            float x2 = fmaxf(fmaf(a, wl.z, p.z), 0.f);
            float x3 = fmaxf(fmaf(a, wl.w, p.w), 0.f);
            int pos = (eIdx + 4 * cc) & 127;
            h1f[(4 * cc + 0) * 128 + pos] = x0;
            h1f[(4 * cc + 1) * 128 + pos] = x1;
            h1f[(4 * cc + 2) * 128 + pos] = x2;
            h1f[(4 * cc + 3) * 128 + pos] = x3;
            float sP = (x0 + x1) + (x2 + x3);
            float qP = fmaf(x0, x0, fmaf(x1, x1, fmaf(x2, x2, x3 * x3)));
            ps2[cc * 129 + eIdx] = sP;
            qs2[cc * 129 + eIdx] = qP;
        }
    }
    __syncthreads();
    {
        float s = 0.f, q = 0.f;
#pragma unroll
        for (int cc = 0; cc < 16; cc++) {
            s += ps2[cc * 129 + tid];
            q += qs2[cc * 129 + tid];
        }
        float mean1 = s * (1.f / 64.f);
        float var1 = fmaf(-mean1, mean1, q * (1.f / 64.f));
        float r1 = rsqrtf(var1 + 1e-5f);
        rst[2 * tid] = r1;
        rst[2 * tid + 1] = -mean1 * r1;
    }
    __syncthreads();   // partials consumed; region becomes w2s
    {   // stage scalar weights: 1024 float4 over 128 threads
        const float4* wsrc = (const float4*)g_wgk;
        float4* wdst = (float4*)w2s;
#pragma unroll
        for (int i = 0; i < 8; i++) wdst[i * 128 + tid] = wsrc[i * 128 + tid];
    }
    __syncthreads();

    // ---- Stage B: acc over dim-pairs; swizzled h read; broadcast weights ---
    int lane = tid & 31, wrp = tid >> 5;
    ull acc[4][8];   // [edge 0..3][dim-pair 0..7], dims = wrp*16 + 2*jp (+1)
#pragma unroll
    for (int ee = 0; ee < 4; ee++)
#pragma unroll
        for (int jp = 0; jp < 8; jp++) acc[ee][jp] = 0ull;
    {
        const float4* hb4 = (const float4*)h1f;
        const float* wbase = w2s + wrp * 16;
#pragma unroll 8
        for (int k = 0; k < 64; k++) {
            float4 hv = hb4[k * 32 + ((lane + (k >> 2)) & 31)];  // edges 4l..+3
            ull h0 = pack2(hv.x, hv.x);
            ull h1 = pack2(hv.y, hv.y);
            ull h2 = pack2(hv.z, hv.z);
            ull h3 = pack2(hv.w, hv.w);
            const ulonglong2* wk = (const ulonglong2*)(wbase + k * 64);
            ulonglong2 wA = wk[0];
            ulonglong2 wB = wk[1];
            ulonglong2 wC = wk[2];
            ulonglong2 wD = wk[3];
            ffma2(acc[0][0], wA.x, h0); ffma2(acc[1][0], wA.x, h1);
            ffma2(acc[2][0], wA.x, h2); ffma2(acc[3][0], wA.x, h3);
            ffma2(acc[0][1], wA.y, h0); ffma2(acc[1][1], wA.y, h1);
            ffma2(acc[2][1], wA.y, h2); ffma2(acc[3][1], wA.y, h3);
            ffma2(acc[0][2], wB.x, h0); ffma2(acc[1][2], wB.x, h1);
            ffma2(acc[2][2], wB.x, h2); ffma2(acc[3][2], wB.x, h3);
            ffma2(acc[0][3], wB.y, h0); ffma2(acc[1][3], wB.y, h1);
            ffma2(acc[2][3], wB.y, h2); ffma2(acc[3][3], wB.y, h3);
            ffma2(acc[0][4], wC.x, h0); ffma2(acc[1][4], wC.x, h1);
            ffma2(acc[2][4], wC.x, h2); ffma2(acc[3][4], wC.x, h3);
            ffma2(acc[0][5], wC.y, h0); ffma2(acc[1][5], wC.y, h1);
            ffma2(acc[2][5], wC.y, h2); ffma2(acc[3][5], wC.y, h3);
            ffma2(acc[0][6], wD.x, h0); ffma2(acc[1][6], wD.x, h1);
            ffma2(acc[2][6], wD.x, h2); ffma2(acc[3][6], wD.x, h3);
            ffma2(acc[0][7], wD.y, h0); ffma2(acc[1][7], wD.y, h1);
            ffma2(acc[2][7], wD.y, h2); ffma2(acc[3][7], wD.y, h3);
        }
    }

    // ---- Stage C (two-pass) ----
    float Ar[16], Br[16];
    {
        const float4* ap = (const float4*)(As + wrp * 16);
        const float4* bp = (const float4*)(Bcs + wrp * 16);
#pragma unroll
        for (int u = 0; u < 4; u++) {
            float4 av = ap[u], bv = bp[u];
            Ar[4 * u] = av.x; Ar[4 * u + 1] = av.y; Ar[4 * u + 2] = av.z; Ar[4 * u + 3] = av.w;
            Br[4 * u] = bv.x; Br[4 * u + 1] = bv.y; Br[4 * u + 2] = bv.z; Br[4 * u + 3] = bv.w;
        }
    }
    float rr[4], mm[4];
#pragma unroll
    for (int i = 0; i < 4; i++) {
        rr[i] = rst[2 * (4 * lane + i)];
        mm[i] = rst[2 * (4 * lane + i) + 1];
    }
    // pass 1: stats only (v recomputed from packed acc, not stored)
    float se[4] = {0.f, 0.f, 0.f, 0.f}, qe[4] = {0.f, 0.f, 0.f, 0.f};
#pragma unroll
    for (int ee = 0; ee < 4; ee++) {
#pragma unroll
        for (int jp = 0; jp < 8; jp++) {
            float lo, hi;
            unpack2(acc[ee][jp], lo, hi);
            int j0 = 2 * jp, j1 = 2 * jp + 1;
            float v0 = fmaxf(fmaf(rr[ee], lo, fmaf(mm[ee], Ar[j0], Br[j0])), 0.f);
            float v1 = fmaxf(fmaf(rr[ee], hi, fmaf(mm[ee], Ar[j1], Br[j1])), 0.f);
            se[ee] += v0 + v1;
            qe[ee] = fmaf(v0, v0, qe[ee]);
            qe[ee] = fmaf(v1, v1, qe[ee]);
        }
    }
    __syncthreads();   // h1f reads done; overlay partials
    float* ps = h1f;            // [4][128]
    float* pq = h1f + 512;      // [4][128]
#pragma unroll
    for (int i = 0; i < 4; i++) {
        ps[wrp * 128 + 4 * lane + i] = se[i];
        pq[wrp * 128 + 4 * lane + i] = qe[i];
    }
    __syncthreads();
    {
        float s = ps[tid] + ps[128 + tid] + ps[256 + tid] + ps[384 + tid];
        float q = pq[tid] + pq[128 + tid] + pq[256 + tid] + pq[384 + tid];
        float mean = s * (1.f / 64.f);
        float var = fmaf(-mean, mean, q * (1.f / 64.f));
        float r = rsqrtf(var + 1e-5f);
        rst[2 * tid] = r;
        rst[2 * tid + 1] = -mean * r;
    }
    __syncthreads();
    // pass 2: LN2 apply into smem rows out[e][65] (overlays dyn; partials dead)
    float* outb = (float*)dyn;
#pragma unroll
    for (int ee = 0; ee < 4; ee++) {
        int eIdx = 4 * lane + ee;
        float r2 = rst[2 * eIdx];
        float mr2 = rst[2 * eIdx + 1];
        float* orow = outb + eIdx * 65 + wrp * 16;
#pragma unroll
        for (int u = 0; u < 4; u++) {
            int jpA = 2 * u, jpB = 2 * u + 1;
            float lo0, hi0, lo1, hi1;
            unpack2(acc[ee][jpA], lo0, hi0);
            unpack2(acc[ee][jpB], lo1, hi1);
            int j0 = 4 * u, j1 = j0 + 1, j2 = j0 + 2, j3 = j0 + 3;
            float v0 = fmaxf(fmaf(rr[ee], lo0, fmaf(mm[ee], Ar[j0], Br[j0])), 0.f);
            float v1 = fmaxf(fmaf(rr[ee], hi0, fmaf(mm[ee], Ar[j1], Br[j1])), 0.f);
            float v2 = fmaxf(fmaf(rr[ee], lo1, fmaf(mm[ee], Ar[j2], Br[j2])), 0.f);
            float v3 = fmaxf(fmaf(rr[ee], hi1, fmaf(mm[ee], Ar[j3], Br[j3])), 0.f);
            float4 gv = ((const float4*)(gs + wrp * 16))[u];
            float4 bv = ((const float4*)(bs + wrp * 16))[u];
            orow[4 * u + 0] = fmaf(fmaf(v0, r2, mr2), gv.x, bv.x);
            orow[4 * u + 1] = fmaf(fmaf(v1, r2, mr2), gv.y, bv.y);
            orow[4 * u + 2] = fmaf(fmaf(v2, r2, mr2), gv.z, bv.z);
            orow[4 * u + 3] = fmaf(fmaf(v3, r2, mr2), gv.w, bv.w);
        }
    }
    __syncthreads();
    // coalesced cooperative red: 16 lanes cover one edge's full row
    {
        int ce = tid >> 4;   // edge-slot within iteration (0..7)
        int cc = tid & 15;   // 4-float chunk (0..15)
#pragma unroll
        for (int i = 0; i < 16; i++) {
            int eIdx = i * 8 + ce;
            int dnL = sdst[eIdx];
            const float* orow = outb + eIdx * 65 + 4 * cc;
            float o0 = orow[0], o1 = orow[1], o2 = orow[2], o3 = orow[3];
            if (dnL >= 0) {
                float* p = g_agg + (long)dnL * 64 + 4 * cc;
                asm volatile("red.global.add.v4.f32 [%0], {%1,%2,%3,%4};"
                             :: "l"(p), "f"(o0), "f"(o1), "f"(o2), "f"(o3)
                             : "memory");
            }
        }
    }
}

// ---------------- qkv = h @ in_proj_w.T + b, 32 nodes/block ------------------
__global__ void __launch_bounds__(192) qkv_kernel(const float* __restrict__ w,
                                                  const float* __restrict__ b, int N) {
    __shared__ __align__(16) float hs[32 * 64];
    int tid = threadIdx.x;
    int n0 = blockIdx.x * 32;
    for (int i = tid; i < 32 * 64 / 4; i += 192)
        ((float4*)hs)[i] = ((const float4*)(g_agg + n0 * 64))[i];
    float wr[64];
    {
        const float4* p4 = (const float4*)(w + tid * 64);
#pragma unroll
        for (int k = 0; k < 16; k++) {
            float4 f = p4[k];
            wr[4 * k] = f.x; wr[4 * k + 1] = f.y; wr[4 * k + 2] = f.z; wr[4 * k + 3] = f.w;
        }
    }
    float br = b[tid];
    __syncthreads();
    int sec = tid / 64, wi = tid % 64, hh = wi / 16, dd = wi % 16;
    float* dst = sec == 0 ? g_q : (sec == 1 ? g_k : g_v);
#pragma unroll 4
    for (int nn = 0; nn < 32; nn++) {
        float acc = br;
#pragma unroll
        for (int k = 0; k < 16; k++) {
            float4 h = *(const float4*)&hs[nn * 64 + 4 * k];
            acc = fmaf(wr[4 * k], h.x, acc);
            acc = fmaf(wr[4 * k + 1], h.y, acc);
            acc = fmaf(wr[4 * k + 2], h.z, acc);
            acc = fmaf(wr[4 * k + 3], h.w, acc);
        }
        dst[hh * N * 16 + (n0 + nn) * 16 + dd] = acc;
    }
}

// ---------------- flash attention, f32x2, log2-domain softmax ---------------
__global__ void __launch_bounds__(128) attn_kernel(int N) {
    int hh = blockIdx.y;
    int part = threadIdx.x >> 5;
    int lane = threadIdx.x & 31;
    int qi = blockIdx.x * 32 + lane;
    const float* Q = g_q + hh * N * 16;
    const float* K = g_k + hh * N * 16;
    const float* V = g_v + hh * N * 16;

    __shared__ __align__(16) float Ks[4][64 * 16];
    __shared__ __align__(16) float Vs[4][64 * 16];
    __shared__ float mrg[3][32][18];

    const float QS = 0.25f * 1.4426950408889634f;
    ull q2[8];
    {
        const float4* qp = (const float4*)(Q + qi * 16);
#pragma unroll
        for (int u = 0; u < 4; u++) {
            float4 f = qp[u];
            q2[2 * u] = pack2(f.x * QS, f.y * QS);
            q2[2 * u + 1] = pack2(f.z * QS, f.w * QS);
        }
    }
    ull o2[8];
#pragma unroll
    for (int u = 0; u < 8; u++) o2[u] = 0ull;
    float m = -1e30f, l = 0.f;

    int j0 = part * (N >> 2);
    for (int kt = 0; kt < (N >> 2); kt += 64) {
        {
            const float4* ksrc = (const float4*)(K + (j0 + kt) * 16);
            const float4* vsrc = (const float4*)(V + (j0 + kt) * 16);
            float4* kdst = (float4*)Ks[part];
            float4* vdst = (float4*)Vs[part];
#pragma unroll
            for (int u = 0; u < 8; u++) {
                kdst[u * 32 + lane] = ksrc[u * 32 + lane];
                vdst[u * 32 + lane] = vsrc[u * 32 + lane];
            }
        }
        __syncwarp();
        for (int c = 0; c < 4; c++) {
            float s[16];
#pragma unroll
            for (int jj = 0; jj < 16; jj++) {
                int j = c * 16 + jj;
                const ulonglong2* kr = (const ulonglong2*)&Ks[part][j * 16];
                ulonglong2 ka = kr[0], kb = kr[1], kc = kr[2], kd = kr[3];
                ull s2 = mul2(q2[0], ka.x);
                ffma2(s2, q2[1], ka.y);
                ffma2(s2, q2[2], kb.x);
                ffma2(s2, q2[3], kb.y);
                ffma2(s2, q2[4], kc.x);
                ffma2(s2, q2[5], kc.y);
                ffma2(s2, q2[6], kd.x);
                ffma2(s2, q2[7], kd.y);
                float slo, shi;
                unpack2(s2, slo, shi);
                s[jj] = slo + shi;
            }
            float tm = s[0];
#pragma unroll
            for (int jj = 1; jj < 16; jj++) tm = fmaxf(tm, s[jj]);
            float nm = fmaxf(m, tm);
            float corr = ex2f(m - nm);
            m = nm;
            l *= corr;
            ull c2 = pack2(corr, corr);
#pragma unroll
            for (int u = 0; u < 8; u++) o2[u] = mul2(o2[u], c2);
#pragma unroll
            for (int jj = 0; jj < 16; jj++) {
                int j = c * 16 + jj;
                float p = ex2f(s[jj] - m);
                l += p;
                ull p2 = pack2(p, p);
                const ulonglong2* vr = (const ulonglong2*)&Vs[part][j * 16];
                ulonglong2 va = vr[0], vb = vr[1], vc = vr[2], vd = vr[3];
                ffma2(o2[0], p2, va.x);
                ffma2(o2[1], p2, va.y);
                ffma2(o2[2], p2, vb.x);
                ffma2(o2[3], p2, vb.y);
                ffma2(o2[4], p2, vc.x);
                ffma2(o2[5], p2, vc.y);
                ffma2(o2[6], p2, vd.x);
                ffma2(o2[7], p2, vd.y);
            }
        }
        __syncwarp();
    }

    if (part != 0) {
        float* d = &mrg[part - 1][lane][0];
        d[0] = m;
        d[1] = l;
#pragma unroll
        for (int u = 0; u < 8; u++) {
            float lo, hi;
            unpack2(o2[u], lo, hi);
            d[2 + 2 * u] = lo;
            d[3 + 2 * u] = hi;
        }
    }
    __syncthreads();
    if (part == 0) {
        float M = m;
#pragma unroll
        for (int p2i = 0; p2i < 3; p2i++) M = fmaxf(M, mrg[p2i][lane][0]);
        float c0 = ex2f(m - M);
        float L = l * c0;
        float o[16];
#pragma unroll
        for (int u = 0; u < 8; u++) {
            float lo, hi;
            unpack2(o2[u], lo, hi);
            o[2 * u] = lo * c0;
            o[2 * u + 1] = hi * c0;
        }
#pragma unroll
        for (int p2i = 0; p2i < 3; p2i++) {
            const float* sp = &mrg[p2i][lane][0];
            float cp = ex2f(sp[0] - M);
            L = fmaf(sp[1], cp, L);
#pragma unroll
            for (int c = 0; c < 16; c++) o[c] = fmaf(sp[2 + c], cp, o[c]);
        }
        float inv = 1.f / L;
#pragma unroll
        for (int c = 0; c < 16; c++) g_obuf[qi * 64 + hh * 16 + c] = o[c] * inv;
    }
}

// ---------------- out_proj + residual + LN + final linear --------------------
__global__ void __launch_bounds__(128) epi_kernel(
    const float* __restrict__ opw, const float* __restrict__ opb,
    const float* __restrict__ ang, const float* __restrict__ anb,
    const float* __restrict__ ow, const float* __restrict__ ob,
    float* __restrict__ out) {
    int tid = threadIdx.x;
    int d = tid & 63, g = tid >> 6;
    int n0 = blockIdx.x * 8;
    __shared__ __align__(16) float os[8 * 64];
    __shared__ __align__(16) float ts[8 * 64];
    __shared__ float ps[8][16], pq[8][16];
    __shared__ float mv[8][2];

    for (int i = tid; i < 8 * 64; i += 128) os[i] = g_obuf[n0 * 64 + i];
    float wr[64];
    {
        const float4* p4 = (const float4*)(opw + d * 64);
#pragma unroll
        for (int k = 0; k < 16; k++) {
            float4 f = p4[k];
            wr[4 * k] = f.x; wr[4 * k + 1] = f.y; wr[4 * k + 2] = f.z; wr[4 * k + 3] = f.w;
        }
    }
    float bb = opb[d];
    __syncthreads();
#pragma unroll
    for (int ni = 0; ni < 4; ni++) {
        int nn = g * 4 + ni;
        float acc = bb;
#pragma unroll
        for (int k = 0; k < 16; k++) {
            float4 h = *(const float4*)&os[nn * 64 + 4 * k];
            acc = fmaf(wr[4 * k], h.x, acc);
            acc = fmaf(wr[4 * k + 1], h.y, acc);
            acc = fmaf(wr[4 * k + 2], h.z, acc);
            acc = fmaf(wr[4 * k + 3], h.w, acc);
        }
        ts[nn * 64 + d] = g_agg[(n0 + nn) * 64 + d] + acc;
    }
    __syncthreads();
    {
        int n = tid >> 4, sg = tid & 15;
        float s = 0.f, qq = 0.f;
#pragma unroll
        for (int t = 0; t < 4; t++) {
            float v2 = ts[n * 64 + sg * 4 + t];
            s += v2; qq += v2 * v2;
        }
        ps[n][sg] = s; pq[n][sg] = qq;
    }
    __syncthreads();
    if (tid < 8) {
        float s = 0.f, qq = 0.f;
#pragma unroll
        for (int t = 0; t < 16; t++) { s += ps[tid][t]; qq += pq[tid][t]; }
        float mean = s * (1.f / 64.f);
        float var = qq * (1.f / 64.f) - mean * mean;
        mv[tid][0] = mean;
        mv[tid][1] = rsqrtf(var + 1e-5f);
    }
    __syncthreads();
    float gg = ang[d], gb = anb[d];
#pragma unroll
    for (int ni = 0; ni < 4; ni++) {
        int nn = g * 4 + ni;
        ts[nn * 64 + d] = (ts[nn * 64 + d] - mv[nn][0]) * mv[nn][1] * gg + gb;
    }
    {
        const float4* p4 = (const float4*)(ow + d * 64);
#pragma unroll
        for (int k = 0; k < 16; k++) {
            float4 f = p4[k];
            wr[4 * k] = f.x; wr[4 * k + 1] = f.y; wr[4 * k + 2] = f.z; wr[4 * k + 3] = f.w;
        }
    }
    float bo = ob[d];
    __syncthreads();
#pragma unroll
    for (int ni = 0; ni < 4; ni++) {
        int nn = g * 4 + ni;
        float acc = bo;
#pragma unroll
        for (int k = 0; k < 16; k++) {
            float4 h = *(const float4*)&ts[nn * 64 + 4 * k];
            acc = fmaf(wr[4 * k], h.x, acc);
            acc = fmaf(wr[4 * k + 1], h.y, acc);
            acc = fmaf(wr[4 * k + 2], h.z, acc);
            acc = fmaf(wr[4 * k + 3], h.w, acc);
        }
        out[(n0 + nn) * 64 + d] = acc;
    }
}

// ---------------- launch ----------------
extern "C" void kernel_launch(void* const* d_in, const int* in_sizes, int n_in,
                              void* d_out, int out_size) {
    const float* x        = (const float*)d_in[0];
    const float* eattr    = (const float*)d_in[1];
    const float* emb      = (const float*)d_in[2];
    const float* lin1_w   = (const float*)d_in[3];
    const float* lin1_b   = (const float*)d_in[4];
    const float* lay_w    = (const float*)d_in[5];
    const float* lay_b    = (const float*)d_in[6];
    const float* ln_g     = (const float*)d_in[7];
    const float* ln_b     = (const float*)d_in[8];
    const float* in_proj_w  = (const float*)d_in[9];
    const float* in_proj_b  = (const float*)d_in[10];
    const float* out_proj_w = (const float*)d_in[11];
    const float* out_proj_b = (const float*)d_in[12];
    const float* an_g     = (const float*)d_in[13];
    const float* an_b     = (const float*)d_in[14];
    const float* out_w    = (const float*)d_in[15];
    const float* out_b    = (const float*)d_in[16];
    const void*  ei       = d_in[17];
    const void*  ety      = d_in[18];

    int E = in_sizes[1];
    int N = in_sizes[0] / 6;

    cudaFuncSetAttribute(edge_kernel, cudaFuncAttributeMaxDynamicSharedMemorySize,
                         EDGE_DYN);

    detectAB_kernel<<<1, 64>>>((const unsigned*)ei, (const unsigned*)ety,
                               lay_w, ln_g, ln_b, lay_b);
    setup_kernel<<<N / 16 + 16 + N / 4, 256>>>(x, emb, lin1_w, lin1_b, ety,
                                               lay_w, ln_g, N);
    edge_kernel<<<(E + 127) / 128, 128, EDGE_DYN>>>(ei, eattr, lin1_w, ln_g,
                                                    ln_b, E);
    qkv_kernel<<<N / 32, 192>>>(in_proj_w, in_proj_b, N);
    attn_kernel<<<dim3(N / 32, 4), 128>>>(N);
    epi_kernel<<<N / 8, 128>>>(out_proj_w, out_proj_b, an_g, an_b, out_w, out_b,
                               (float*)d_out);
}

// round 14
// speedup vs baseline: 1.1706x; 1.1059x over previous
#include <cuda_runtime.h>
#include <cstdint>

#define NMAX 4096
#define HID 64

typedef unsigned long long ull;

// ---------------- device scratch ----------------
__device__ __align__(256) float g_P[NMAX * HID];
__device__ __align__(256) float g_agg[NMAX * HID];
__device__ __align__(256) float g_q[4 * NMAX * 16];
__device__ __align__(256) float g_k[4 * NMAX * 16];
__device__ __align__(256) float g_v[4 * NMAX * 16];
__device__ __align__(256) float g_obuf[NMAX * HID];
__device__ __align__(256) float g_wgk[64 * 64];  // [k][d] = w2[d][k]*g[k] (scalar)
__device__ __align__(256) float g_A[64];         // A[d] = sum_k w2[d][k]*g[k]
__device__ __align__(256) float g_Bc[64];        // B[d] + b2[d]
__device__ int g_is64_ei;
__device__ int g_is64_ty;

__device__ __forceinline__ long ldidx(const void* p, long i, int is64) {
    return is64 ? (long)((const long long*)p)[i] : (long)((const int*)p)[i];
}

// ---------------- packed f32x2 helpers ----------------
__device__ __forceinline__ ull pack2(float lo, float hi) {
    ull r; asm("mov.b64 %0, {%1, %2};" : "=l"(r) : "f"(lo), "f"(hi)); return r;
}
__device__ __forceinline__ void unpack2(ull v, float& lo, float& hi) {
    asm("mov.b64 {%0, %1}, %2;" : "=f"(lo), "=f"(hi) : "l"(v));
}
__device__ __forceinline__ void ffma2(ull& d, ull a, ull b) {
    asm("fma.rn.f32x2 %0, %1, %2, %0;" : "+l"(d) : "l"(a), "l"(b));
}
__device__ __forceinline__ ull mul2(ull a, ull b) {
    ull r; asm("mul.rn.f32x2 %0, %1, %2;" : "=l"(r) : "l"(a), "l"(b)); return r;
}
__device__ __forceinline__ float ex2f(float x) {
    float r; asm("ex2.approx.ftz.f32 %0, %1;" : "=f"(r) : "f"(x)); return r;
}

// ---------------- detect dtypes + per-dim LN1-fold constants ----------------
__global__ void detectAB_kernel(const unsigned* ei, const unsigned* ty,
                                const float* __restrict__ w2g,
                                const float* __restrict__ lng,
                                const float* __restrict__ lnb,
                                const float* __restrict__ b2) {
    int d = threadIdx.x;   // 64
    float A = 0.f, B = 0.f;
#pragma unroll 8
    for (int k = 0; k < 64; k++) {
        float w = w2g[d * 64 + k];
        A = fmaf(w, lng[k], A);
        B = fmaf(w, lnb[k], B);
    }
    g_A[d] = A;
    g_Bc[d] = B + b2[d];
    if (d == 0) {
        unsigned a = 0;
        for (int i = 0; i < 32; i++) a |= ei[2 * i + 1];
        g_is64_ei = (a == 0) ? 1 : 0;
        unsigned b = 0;
        for (int i = 0; i < 32; i++) b |= ty[2 * i + 1];
        g_is64_ty = (b == 0) ? 1 : 0;
    }
}

// ---------------- fused setup: zero g_agg | pack w*g k-major | prep P -------
__global__ void __launch_bounds__(256) setup_kernel(
    const float* __restrict__ x, const float* __restrict__ emb,
    const float* __restrict__ w1, const float* __restrict__ b1,
    const void* __restrict__ ety, const float* __restrict__ w2g,
    const float* __restrict__ lng, int N) {
    int bid = blockIdx.x, t = threadIdx.x;
    int zb = N / 16;
    if (bid < zb) {
        ((float4*)g_agg)[bid * 256 + t] = make_float4(0.f, 0.f, 0.f, 0.f);
    } else if (bid < zb + 16) {
        int i = (bid - zb) * 256 + t;        // i = k*64 + d
        int k = i >> 6, d = i & 63;
        g_wgk[i] = w2g[d * 64 + k] * lng[k];
    } else {
        int nb = bid - zb - 16;
        int grp = t >> 6, d = t & 63;
        int n = nb * 4 + grp;
        __shared__ float xs[4][16];
        int is64 = g_is64_ty;
        if (d < 6) {
            xs[grp][d] = x[n * 6 + d];
        } else if (d < 14) {
            long tt = ldidx(ety, n, is64);
            xs[grp][d] = emb[tt * 8 + (d - 6)];
        }
        __syncthreads();
        float acc = b1[d];
#pragma unroll
        for (int k = 0; k < 14; k++) acc = fmaf(xs[grp][k], w1[d * 15 + k], acc);
        g_P[n * HID + d] = acc;
    }
}

// ---------------- edge MLP + scatter-add (R13 structure, unchanged) ---------
#define EDGE_DYN 49280
__global__ void __launch_bounds__(128, 4) edge_kernel(
    const void* __restrict__ ei, const float* __restrict__ eattr,
    const float* __restrict__ w1, const float* __restrict__ lng,
    const float* __restrict__ lnb, int nE) {
    extern __shared__ __align__(16) char dyn[];
    float* h1f = (float*)dyn;                 // 32KB swizzled [k][128]
    float* w2s = (float*)(dyn + 32768);       // 16KB [k][64] (after stage A)
    float* ps2 = (float*)(dyn + 32768);       // stage A: partial s [cc*129+e]
    float* qs2 = ps2 + 2064;                  // stage A: partial q
    __shared__ __align__(16) float w1ls[64];
    __shared__ __align__(16) float As[64];
    __shared__ __align__(16) float Bcs[64];
    __shared__ __align__(16) float gs[64];
    __shared__ __align__(16) float bs[64];
    __shared__ __align__(8) float rst[128 * 2];
    __shared__ int sdst[128];
    __shared__ int ssrc[128];
    __shared__ float sat[128];

    int tid = threadIdx.x;
    if (tid < 64) {
        w1ls[tid] = w1[tid * 15 + 14];
        As[tid] = g_A[tid];
        Bcs[tid] = g_Bc[tid];
        gs[tid] = lng[tid];
        bs[tid] = lnb[tid];
    }
    long e = (long)blockIdx.x * 128 + tid;
    bool act = e < nE;
    int is64 = g_is64_ei;
    {
        long dl = -1, srcl = 0;
        float a = 0.f;
        if (act) {
            srcl = ldidx(ei, e, is64);
            dl = ldidx(ei, (long)nE + e, is64);
            a = eattr[e];
        }
        ssrc[tid] = (int)srcl;
        sdst[tid] = (int)dl;
        sat[tid] = a;
    }
    __syncthreads();

    // ---- Stage A: coalesced gather; relu; swizzled k-major store; partials -
    {
        int ce = tid >> 4, cc = tid & 15;
        float4 wl = ((const float4*)w1ls)[cc];
#pragma unroll
        for (int i = 0; i < 16; i++) {
            int eIdx = i * 8 + ce;
            float4 p = ((const float4*)(g_P + (long)ssrc[eIdx] * 64))[cc];
            float a = sat[eIdx];
            float x0 = fmaxf(fmaf(a, wl.x, p.x), 0.f);
            float x1 = fmaxf(fmaf(a, wl.y, p.y), 0.f);
            float x2 = fmaxf(fmaf(a, wl.z, p.z), 0.f);
            float x3 = fmaxf(fmaf(a, wl.w, p.w), 0.f);
            int pos = (eIdx + 4 * cc) & 127;
            h1f[(4 * cc + 0) * 128 + pos] = x0;
            h1f[(4 * cc + 1) * 128 + pos] = x1;
            h1f[(4 * cc + 2) * 128 + pos] = x2;
            h1f[(4 * cc + 3) * 128 + pos] = x3;
            float sP = (x0 + x1) + (x2 + x3);
            float qP = fmaf(x0, x0, fmaf(x1, x1, fmaf(x2, x2, x3 * x3)));
            ps2[cc * 129 + eIdx] = sP;
            qs2[cc * 129 + eIdx] = qP;
        }
    }
    __syncthreads();
    {
        float s = 0.f, q = 0.f;
#pragma unroll
        for (int cc = 0; cc < 16; cc++) {
            s += ps2[cc * 129 + tid];
            q += qs2[cc * 129 + tid];
        }
        float mean1 = s * (1.f / 64.f);
        float var1 = fmaf(-mean1, mean1, q * (1.f / 64.f));
        float r1 = rsqrtf(var1 + 1e-5f);
        rst[2 * tid] = r1;
        rst[2 * tid + 1] = -mean1 * r1;
    }
    __syncthreads();   // partials consumed; region becomes w2s
    {
        const float4* wsrc = (const float4*)g_wgk;
        float4* wdst = (float4*)w2s;
#pragma unroll
        for (int i = 0; i < 8; i++) wdst[i * 128 + tid] = wsrc[i * 128 + tid];
    }
    __syncthreads();

    // ---- Stage B ----
    int lane = tid & 31, wrp = tid >> 5;
    ull acc[4][8];
#pragma unroll
    for (int ee = 0; ee < 4; ee++)
#pragma unroll
        for (int jp = 0; jp < 8; jp++) acc[ee][jp] = 0ull;
    {
        const float4* hb4 = (const float4*)h1f;
        const float* wbase = w2s + wrp * 16;
#pragma unroll 8
        for (int k = 0; k < 64; k++) {
            float4 hv = hb4[k * 32 + ((lane + (k >> 2)) & 31)];
            ull h0 = pack2(hv.x, hv.x);
            ull h1 = pack2(hv.y, hv.y);
            ull h2 = pack2(hv.z, hv.z);
            ull h3 = pack2(hv.w, hv.w);
            const ulonglong2* wk = (const ulonglong2*)(wbase + k * 64);
            ulonglong2 wA = wk[0];
            ulonglong2 wB = wk[1];
            ulonglong2 wC = wk[2];
            ulonglong2 wD = wk[3];
            ffma2(acc[0][0], wA.x, h0); ffma2(acc[1][0], wA.x, h1);
            ffma2(acc[2][0], wA.x, h2); ffma2(acc[3][0], wA.x, h3);
            ffma2(acc[0][1], wA.y, h0); ffma2(acc[1][1], wA.y, h1);
            ffma2(acc[2][1], wA.y, h2); ffma2(acc[3][1], wA.y, h3);
            ffma2(acc[0][2], wB.x, h0); ffma2(acc[1][2], wB.x, h1);
            ffma2(acc[2][2], wB.x, h2); ffma2(acc[3][2], wB.x, h3);
            ffma2(acc[0][3], wB.y, h0); ffma2(acc[1][3], wB.y, h1);
            ffma2(acc[2][3], wB.y, h2); ffma2(acc[3][3], wB.y, h3);
            ffma2(acc[0][4], wC.x, h0); ffma2(acc[1][4], wC.x, h1);
            ffma2(acc[2][4], wC.x, h2); ffma2(acc[3][4], wC.x, h3);
            ffma2(acc[0][5], wC.y, h0); ffma2(acc[1][5], wC.y, h1);
            ffma2(acc[2][5], wC.y, h2); ffma2(acc[3][5], wC.y, h3);
            ffma2(acc[0][6], wD.x, h0); ffma2(acc[1][6], wD.x, h1);
            ffma2(acc[2][6], wD.x, h2); ffma2(acc[3][6], wD.x, h3);
            ffma2(acc[0][7], wD.y, h0); ffma2(acc[1][7], wD.y, h1);
            ffma2(acc[2][7], wD.y, h2); ffma2(acc[3][7], wD.y, h3);
        }
    }

    // ---- Stage C (two-pass) ----
    float Ar[16], Br[16];
    {
        const float4* ap = (const float4*)(As + wrp * 16);
        const float4* bp = (const float4*)(Bcs + wrp * 16);
#pragma unroll
        for (int u = 0; u < 4; u++) {
            float4 av = ap[u], bv = bp[u];
            Ar[4 * u] = av.x; Ar[4 * u + 1] = av.y; Ar[4 * u + 2] = av.z; Ar[4 * u + 3] = av.w;
            Br[4 * u] = bv.x; Br[4 * u + 1] = bv.y; Br[4 * u + 2] = bv.z; Br[4 * u + 3] = bv.w;
        }
    }
    float rr[4], mm[4];
#pragma unroll
    for (int i = 0; i < 4; i++) {
        rr[i] = rst[2 * (4 * lane + i)];
        mm[i] = rst[2 * (4 * lane + i) + 1];
    }
    float se[4] = {0.f, 0.f, 0.f, 0.f}, qe[4] = {0.f, 0.f, 0.f, 0.f};
#pragma unroll
    for (int ee = 0; ee < 4; ee++) {
#pragma unroll
        for (int jp = 0; jp < 8; jp++) {
            float lo, hi;
            unpack2(acc[ee][jp], lo, hi);
            int j0 = 2 * jp, j1 = 2 * jp + 1;
            float v0 = fmaxf(fmaf(rr[ee], lo, fmaf(mm[ee], Ar[j0], Br[j0])), 0.f);
            float v1 = fmaxf(fmaf(rr[ee], hi, fmaf(mm[ee], Ar[j1], Br[j1])), 0.f);
            se[ee] += v0 + v1;
            qe[ee] = fmaf(v0, v0, qe[ee]);
            qe[ee] = fmaf(v1, v1, qe[ee]);
        }
    }
    __syncthreads();
    float* ps = h1f;
    float* pq = h1f + 512;
#pragma unroll
    for (int i = 0; i < 4; i++) {
        ps[wrp * 128 + 4 * lane + i] = se[i];
        pq[wrp * 128 + 4 * lane + i] = qe[i];
    }
    __syncthreads();
    {
        float s = ps[tid] + ps[128 + tid] + ps[256 + tid] + ps[384 + tid];
        float q = pq[tid] + pq[128 + tid] + pq[256 + tid] + pq[384 + tid];
        float mean = s * (1.f / 64.f);
        float var = fmaf(-mean, mean, q * (1.f / 64.f));
        float r = rsqrtf(var + 1e-5f);
        rst[2 * tid] = r;
        rst[2 * tid + 1] = -mean * r;
    }
    __syncthreads();
    float* outb = (float*)dyn;
#pragma unroll
    for (int ee = 0; ee < 4; ee++) {
        int eIdx = 4 * lane + ee;
        float r2 = rst[2 * eIdx];
        float mr2 = rst[2 * eIdx + 1];
        float* orow = outb + eIdx * 65 + wrp * 16;
#pragma unroll
        for (int u = 0; u < 4; u++) {
            int jpA = 2 * u, jpB = 2 * u + 1;
            float lo0, hi0, lo1, hi1;
            unpack2(acc[ee][jpA], lo0, hi0);
            unpack2(acc[ee][jpB], lo1, hi1);
            int j0 = 4 * u, j1 = j0 + 1, j2 = j0 + 2, j3 = j0 + 3;
            float v0 = fmaxf(fmaf(rr[ee], lo0, fmaf(mm[ee], Ar[j0], Br[j0])), 0.f);
            float v1 = fmaxf(fmaf(rr[ee], hi0, fmaf(mm[ee], Ar[j1], Br[j1])), 0.f);
            float v2 = fmaxf(fmaf(rr[ee], lo1, fmaf(mm[ee], Ar[j2], Br[j2])), 0.f);
            float v3 = fmaxf(fmaf(rr[ee], hi1, fmaf(mm[ee], Ar[j3], Br[j3])), 0.f);
            float4 gv = ((const float4*)(gs + wrp * 16))[u];
            float4 bv = ((const float4*)(bs + wrp * 16))[u];
            orow[4 * u + 0] = fmaf(fmaf(v0, r2, mr2), gv.x, bv.x);
            orow[4 * u + 1] = fmaf(fmaf(v1, r2, mr2), gv.y, bv.y);
            orow[4 * u + 2] = fmaf(fmaf(v2, r2, mr2), gv.z, bv.z);
            orow[4 * u + 3] = fmaf(fmaf(v3, r2, mr2), gv.w, bv.w);
        }
    }
    __syncthreads();
    {
        int ce = tid >> 4;
        int cc = tid & 15;
#pragma unroll
        for (int i = 0; i < 16; i++) {
            int eIdx = i * 8 + ce;
            int dnL = sdst[eIdx];
            const float* orow = outb + eIdx * 65 + 4 * cc;
            float o0 = orow[0], o1 = orow[1], o2 = orow[2], o3 = orow[3];
            if (dnL >= 0) {
                float* p = g_agg + (long)dnL * 64 + 4 * cc;
                asm volatile("red.global.add.v4.f32 [%0], {%1,%2,%3,%4};"
                             :: "l"(p), "f"(o0), "f"(o1), "f"(o2), "f"(o3)
                             : "memory");
            }
        }
    }
}

// ---------------- qkv = h @ in_proj_w.T + b, 32 nodes/block ------------------
__global__ void __launch_bounds__(192) qkv_kernel(const float* __restrict__ w,
                                                  const float* __restrict__ b, int N) {
    __shared__ __align__(16) float hs[32 * 64];
    int tid = threadIdx.x;
    int n0 = blockIdx.x * 32;
    for (int i = tid; i < 32 * 64 / 4; i += 192)
        ((float4*)hs)[i] = ((const float4*)(g_agg + n0 * 64))[i];
    float wr[64];
    {
        const float4* p4 = (const float4*)(w + tid * 64);
#pragma unroll
        for (int k = 0; k < 16; k++) {
            float4 f = p4[k];
            wr[4 * k] = f.x; wr[4 * k + 1] = f.y; wr[4 * k + 2] = f.z; wr[4 * k + 3] = f.w;
        }
    }
    float br = b[tid];
    __syncthreads();
    int sec = tid / 64, wi = tid % 64, hh = wi / 16, dd = wi % 16;
    float* dst = sec == 0 ? g_q : (sec == 1 ? g_k : g_v);
#pragma unroll 4
    for (int nn = 0; nn < 32; nn++) {
        float acc = br;
#pragma unroll
        for (int k = 0; k < 16; k++) {
            float4 h = *(const float4*)&hs[nn * 64 + 4 * k];
            acc = fmaf(wr[4 * k], h.x, acc);
            acc = fmaf(wr[4 * k + 1], h.y, acc);
            acc = fmaf(wr[4 * k + 2], h.z, acc);
            acc = fmaf(wr[4 * k + 3], h.w, acc);
        }
        dst[hh * N * 16 + (n0 + nn) * 16 + dd] = acc;
    }
}

// ---------------- flash attention: 2 queries/thread, 4-way K-split ----------
// Block = 128 thr = 4 K-quarter warps; thread owns queries (qa, qa+32).
// grid = (N/64, 4 heads). K/V tile LDS serve both queries; L2 traffic halved.
__global__ void __launch_bounds__(128) attn_kernel(int N) {
    int hh = blockIdx.y;
    int part = threadIdx.x >> 5;
    int lane = threadIdx.x & 31;
    int qa = blockIdx.x * 64 + lane;
    int qb = qa + 32;
    const float* Q = g_q + hh * N * 16;
    const float* K = g_k + hh * N * 16;
    const float* V = g_v + hh * N * 16;

    __shared__ __align__(16) float Ks[4][64 * 16];
    __shared__ __align__(16) float Vs[4][64 * 16];
    __shared__ float mrg[3][64][18];

    const float QS = 0.25f * 1.4426950408889634f;
    ull qA[8], qB[8];
    {
        const float4* qpa = (const float4*)(Q + qa * 16);
        const float4* qpb = (const float4*)(Q + qb * 16);
#pragma unroll
        for (int u = 0; u < 4; u++) {
            float4 fa = qpa[u], fb = qpb[u];
            qA[2 * u] = pack2(fa.x * QS, fa.y * QS);
            qA[2 * u + 1] = pack2(fa.z * QS, fa.w * QS);
            qB[2 * u] = pack2(fb.x * QS, fb.y * QS);
            qB[2 * u + 1] = pack2(fb.z * QS, fb.w * QS);
        }
    }
    ull oA[8], oB[8];
#pragma unroll
    for (int u = 0; u < 8; u++) { oA[u] = 0ull; oB[u] = 0ull; }
    float mA = -1e30f, lA = 0.f, mB = -1e30f, lB = 0.f;

    int j0 = part * (N >> 2);
    for (int kt = 0; kt < (N >> 2); kt += 64) {
        {
            const float4* ksrc = (const float4*)(K + (j0 + kt) * 16);
            const float4* vsrc = (const float4*)(V + (j0 + kt) * 16);
            float4* kdst = (float4*)Ks[part];
            float4* vdst = (float4*)Vs[part];
#pragma unroll
            for (int u = 0; u < 8; u++) {
                kdst[u * 32 + lane] = ksrc[u * 32 + lane];
                vdst[u * 32 + lane] = vsrc[u * 32 + lane];
            }
        }
        __syncwarp();
        for (int c = 0; c < 8; c++) {
            float sA[8], sB[8];
#pragma unroll
            for (int jj = 0; jj < 8; jj++) {
                int j = c * 8 + jj;
                const ulonglong2* kr = (const ulonglong2*)&Ks[part][j * 16];
                ulonglong2 ka = kr[0], kb = kr[1], kc = kr[2], kd = kr[3];
                ull sa = mul2(qA[0], ka.x);
                ffma2(sa, qA[1], ka.y);
                ffma2(sa, qA[2], kb.x);
                ffma2(sa, qA[3], kb.y);
                ffma2(sa, qA[4], kc.x);
                ffma2(sa, qA[5], kc.y);
                ffma2(sa, qA[6], kd.x);
                ffma2(sa, qA[7], kd.y);
                ull sb = mul2(qB[0], ka.x);
                ffma2(sb, qB[1], ka.y);
                ffma2(sb, qB[2], kb.x);
                ffma2(sb, qB[3], kb.y);
                ffma2(sb, qB[4], kc.x);
                ffma2(sb, qB[5], kc.y);
                ffma2(sb, qB[6], kd.x);
                ffma2(sb, qB[7], kd.y);
                float alo, ahi, blo, bhi;
                unpack2(sa, alo, ahi);
                unpack2(sb, blo, bhi);
                sA[jj] = alo + ahi;
                sB[jj] = blo + bhi;
            }
            float tmA = sA[0], tmB = sB[0];
#pragma unroll
            for (int jj = 1; jj < 8; jj++) {
                tmA = fmaxf(tmA, sA[jj]);
                tmB = fmaxf(tmB, sB[jj]);
            }
            float nmA = fmaxf(mA, tmA), nmB = fmaxf(mB, tmB);
            float cA = ex2f(mA - nmA), cB = ex2f(mB - nmB);
            mA = nmA; mB = nmB;
            lA *= cA; lB *= cB;
            ull cA2 = pack2(cA, cA), cB2 = pack2(cB, cB);
#pragma unroll
            for (int u = 0; u < 8; u++) {
                oA[u] = mul2(oA[u], cA2);
                oB[u] = mul2(oB[u], cB2);
            }
#pragma unroll
            for (int jj = 0; jj < 8; jj++) {
                int j = c * 8 + jj;
                float pA = ex2f(sA[jj] - mA);
                float pB = ex2f(sB[jj] - mB);
                lA += pA; lB += pB;
                ull pA2 = pack2(pA, pA), pB2 = pack2(pB, pB);
                const ulonglong2* vr = (const ulonglong2*)&Vs[part][j * 16];
                ulonglong2 va = vr[0], vb = vr[1], vc = vr[2], vd = vr[3];
                ffma2(oA[0], pA2, va.x);  ffma2(oB[0], pB2, va.x);
                ffma2(oA[1], pA2, va.y);  ffma2(oB[1], pB2, va.y);
                ffma2(oA[2], pA2, vb.x);  ffma2(oB[2], pB2, vb.x);
                ffma2(oA[3], pA2, vb.y);  ffma2(oB[3], pB2, vb.y);
                ffma2(oA[4], pA2, vc.x);  ffma2(oB[4], pB2, vc.x);
                ffma2(oA[5], pA2, vc.y);  ffma2(oB[5], pB2, vc.y);
                ffma2(oA[6], pA2, vd.x);  ffma2(oB[6], pB2, vd.x);
                ffma2(oA[7], pA2, vd.y);  ffma2(oB[7], pB2, vd.y);
            }
        }
        __syncwarp();
    }

    if (part != 0) {
        float* da = &mrg[part - 1][lane][0];
        float* db = &mrg[part - 1][32 + lane][0];
        da[0] = mA; da[1] = lA;
        db[0] = mB; db[1] = lB;
#pragma unroll
        for (int u = 0; u < 8; u++) {
            float lo, hi;
            unpack2(oA[u], lo, hi);
            da[2 + 2 * u] = lo; da[3 + 2 * u] = hi;
            unpack2(oB[u], lo, hi);
            db[2 + 2 * u] = lo; db[3 + 2 * u] = hi;
        }
    }
    __syncthreads();
    if (part == 0) {
        // merge query A
        {
            float M = mA;
#pragma unroll
            for (int p2i = 0; p2i < 3; p2i++) M = fmaxf(M, mrg[p2i][lane][0]);
            float c0 = ex2f(mA - M);
            float L = lA * c0;
            float o[16];
#pragma unroll
            for (int u = 0; u < 8; u++) {
                float lo, hi;
                unpack2(oA[u], lo, hi);
                o[2 * u] = lo * c0;
                o[2 * u + 1] = hi * c0;
            }
#pragma unroll
            for (int p2i = 0; p2i < 3; p2i++) {
                const float* sp = &mrg[p2i][lane][0];
                float cp = ex2f(sp[0] - M);
                L = fmaf(sp[1], cp, L);
#pragma unroll
                for (int c = 0; c < 16; c++) o[c] = fmaf(sp[2 + c], cp, o[c]);
            }
            float inv = 1.f / L;
#pragma unroll
            for (int c = 0; c < 16; c++) g_obuf[qa * 64 + hh * 16 + c] = o[c] * inv;
        }
        // merge query B
        {
            float M = mB;
#pragma unroll
            for (int p2i = 0; p2i < 3; p2i++) M = fmaxf(M, mrg[p2i][32 + lane][0]);
            float c0 = ex2f(mB - M);
            float L = lB * c0;
            float o[16];
#pragma unroll
            for (int u = 0; u < 8; u++) {
                float lo, hi;
                unpack2(oB[u], lo, hi);
                o[2 * u] = lo * c0;
                o[2 * u + 1] = hi * c0;
            }
#pragma unroll
            for (int p2i = 0; p2i < 3; p2i++) {
                const float* sp = &mrg[p2i][32 + lane][0];
                float cp = ex2f(sp[0] - M);
                L = fmaf(sp[1], cp, L);
#pragma unroll
                for (int c = 0; c < 16; c++) o[c] = fmaf(sp[2 + c], cp, o[c]);
            }
            float inv = 1.f / L;
#pragma unroll
            for (int c = 0; c < 16; c++) g_obuf[qb * 64 + hh * 16 + c] = o[c] * inv;
        }
    }
}

// ---------------- out_proj + residual + LN + final linear --------------------
__global__ void __launch_bounds__(128) epi_kernel(
    const float* __restrict__ opw, const float* __restrict__ opb,
    const float* __restrict__ ang, const float* __restrict__ anb,
    const float* __restrict__ ow, const float* __restrict__ ob,
    float* __restrict__ out) {
    int tid = threadIdx.x;
    int d = tid & 63, g = tid >> 6;
    int n0 = blockIdx.x * 8;
    __shared__ __align__(16) float os[8 * 64];
    __shared__ __align__(16) float ts[8 * 64];
    __shared__ float ps[8][16], pq[8][16];
    __shared__ float mv[8][2];

    for (int i = tid; i < 8 * 64; i += 128) os[i] = g_obuf[n0 * 64 + i];
    float wr[64];
    {
        const float4* p4 = (const float4*)(opw + d * 64);
#pragma unroll
        for (int k = 0; k < 16; k++) {
            float4 f = p4[k];
            wr[4 * k] = f.x; wr[4 * k + 1] = f.y; wr[4 * k + 2] = f.z; wr[4 * k + 3] = f.w;
        }
    }
    float bb = opb[d];
    __syncthreads();
#pragma unroll
    for (int ni = 0; ni < 4; ni++) {
        int nn = g * 4 + ni;
        float acc = bb;
#pragma unroll
        for (int k = 0; k < 16; k++) {
            float4 h = *(const float4*)&os[nn * 64 + 4 * k];
            acc = fmaf(wr[4 * k], h.x, acc);
            acc = fmaf(wr[4 * k + 1], h.y, acc);
            acc = fmaf(wr[4 * k + 2], h.z, acc);
            acc = fmaf(wr[4 * k + 3], h.w, acc);
        }
        ts[nn * 64 + d] = g_agg[(n0 + nn) * 64 + d] + acc;
    }
    __syncthreads();
    {
        int n = tid >> 4, sg = tid & 15;
        float s = 0.f, qq = 0.f;
#pragma unroll
        for (int t = 0; t < 4; t++) {
            float v2 = ts[n * 64 + sg * 4 + t];
            s += v2; qq += v2 * v2;
        }
        ps[n][sg] = s; pq[n][sg] = qq;
    }
    __syncthreads();
    if (tid < 8) {
        float s = 0.f, qq = 0.f;
#pragma unroll
        for (int t = 0; t < 16; t++) { s += ps[tid][t]; qq += pq[tid][t]; }
        float mean = s * (1.f / 64.f);
        float var = qq * (1.f / 64.f) - mean * mean;
        mv[tid][0] = mean;
        mv[tid][1] = rsqrtf(var + 1e-5f);
    }
    __syncthreads();
    float gg = ang[d], gb = anb[d];
#pragma unroll
    for (int ni = 0; ni < 4; ni++) {
        int nn = g * 4 + ni;
        ts[nn * 64 + d] = (ts[nn * 64 + d] - mv[nn][0]) * mv[nn][1] * gg + gb;
    }
    {
        const float4* p4 = (const float4*)(ow + d * 64);
#pragma unroll
        for (int k = 0; k < 16; k++) {
            float4 f = p4[k];
            wr[4 * k] = f.x; wr[4 * k + 1] = f.y; wr[4 * k + 2] = f.z; wr[4 * k + 3] = f.w;
        }
    }
    float bo = ob[d];
    __syncthreads();
#pragma unroll
    for (int ni = 0; ni < 4; ni++) {
        int nn = g * 4 + ni;
        float acc = bo;
#pragma unroll
        for (int k = 0; k < 16; k++) {
            float4 h = *(const float4*)&ts[nn * 64 + 4 * k];
            acc = fmaf(wr[4 * k], h.x, acc);
            acc = fmaf(wr[4 * k + 1], h.y, acc);
            acc = fmaf(wr[4 * k + 2], h.z, acc);
            acc = fmaf(wr[4 * k + 3], h.w, acc);
        }
        out[(n0 + nn) * 64 + d] = acc;
    }
}

// ---------------- launch ----------------
extern "C" void kernel_launch(void* const* d_in, const int* in_sizes, int n_in,
                              void* d_out, int out_size) {
    const float* x        = (const float*)d_in[0];
    const float* eattr    = (const float*)d_in[1];
    const float* emb      = (const float*)d_in[2];
    const float* lin1_w   = (const float*)d_in[3];
    const float* lin1_b   = (const float*)d_in[4];
    const float* lay_w    = (const float*)d_in[5];
    const float* lay_b    = (const float*)d_in[6];
    const float* ln_g     = (const float*)d_in[7];
    const float* ln_b     = (const float*)d_in[8];
    const float* in_proj_w  = (const float*)d_in[9];
    const float* in_proj_b  = (const float*)d_in[10];
    const float* out_proj_w = (const float*)d_in[11];
    const float* out_proj_b = (const float*)d_in[12];
    const float* an_g     = (const float*)d_in[13];
    const float* an_b     = (const float*)d_in[14];
    const float* out_w    = (const float*)d_in[15];
    const float* out_b    = (const float*)d_in[16];
    const void*  ei       = d_in[17];
    const void*  ety      = d_in[18];

    int E = in_sizes[1];
    int N = in_sizes[0] / 6;

    cudaFuncSetAttribute(edge_kernel, cudaFuncAttributeMaxDynamicSharedMemorySize,
                         EDGE_DYN);

    detectAB_kernel<<<1, 64>>>((const unsigned*)ei, (const unsigned*)ety,
                               lay_w, ln_g, ln_b, lay_b);
    setup_kernel<<<N / 16 + 16 + N / 4, 256>>>(x, emb, lin1_w, lin1_b, ety,
                                               lay_w, ln_g, N);
    edge_kernel<<<(E + 127) / 128, 128, EDGE_DYN>>>(ei, eattr, lin1_w, ln_g,
                                                    ln_b, E);
    qkv_kernel<<<N / 32, 192>>>(in_proj_w, in_proj_b, N);
    attn_kernel<<<dim3(N / 64, 4), 128>>>(N);
    epi_kernel<<<N / 8, 128>>>(out_proj_w, out_proj_b, an_g, an_b, out_w, out_b,
                               (float*)d_out);
}

// round 16
// speedup vs baseline: 1.2113x; 1.0347x over previous
#include <cuda_runtime.h>
#include <cstdint>

#define NMAX 4096
#define HID 64

typedef unsigned long long ull;

// ---------------- device scratch ----------------
__device__ __align__(256) float g_P[NMAX * HID];
__device__ __align__(256) float g_agg[NMAX * HID];
__device__ __align__(256) float g_q[4 * NMAX * 16];
__device__ __align__(256) float g_k[4 * NMAX * 16];
__device__ __align__(256) float g_v[4 * NMAX * 16];
__device__ __align__(256) float g_obuf[NMAX * HID];
__device__ __align__(256) float g_wgk[64 * 64];  // [k][d] = w2[d][k]*g[k] (scalar)
__device__ __align__(256) float g_A[64];         // A[d] = sum_k w2[d][k]*g[k]
__device__ __align__(256) float g_Bc[64];        // B[d] + b2[d]
__device__ int g_is64_ei;
__device__ int g_is64_ty;

__device__ __forceinline__ long ldidx(const void* p, long i, int is64) {
    return is64 ? (long)((const long long*)p)[i] : (long)((const int*)p)[i];
}

// ---------------- packed f32x2 helpers ----------------
__device__ __forceinline__ ull pack2(float lo, float hi) {
    ull r; asm("mov.b64 %0, {%1, %2};" : "=l"(r) : "f"(lo), "f"(hi)); return r;
}
__device__ __forceinline__ void unpack2(ull v, float& lo, float& hi) {
    asm("mov.b64 {%0, %1}, %2;" : "=f"(lo), "=f"(hi) : "l"(v));
}
__device__ __forceinline__ void ffma2(ull& d, ull a, ull b) {
    asm("fma.rn.f32x2 %0, %1, %2, %0;" : "+l"(d) : "l"(a), "l"(b));
}
__device__ __forceinline__ ull mul2(ull a, ull b) {
    ull r; asm("mul.rn.f32x2 %0, %1, %2;" : "=l"(r) : "l"(a), "l"(b)); return r;
}
__device__ __forceinline__ float ex2f(float x) {
    float r; asm("ex2.approx.ftz.f32 %0, %1;" : "=f"(r) : "f"(x)); return r;
}

// ---------------- detect dtypes + per-dim LN1-fold constants ----------------
__global__ void detectAB_kernel(const unsigned* ei, const unsigned* ty,
                                const float* __restrict__ w2g,
                                const float* __restrict__ lng,
                                const float* __restrict__ lnb,
                                const float* __restrict__ b2) {
    int d = threadIdx.x;   // 64
    float A = 0.f, B = 0.f;
#pragma unroll 8
    for (int k = 0; k < 64; k++) {
        float w = w2g[d * 64 + k];
        A = fmaf(w, lng[k], A);
        B = fmaf(w, lnb[k], B);
    }
    g_A[d] = A;
    g_Bc[d] = B + b2[d];
    if (d == 0) {
        unsigned a = 0;
        for (int i = 0; i < 32; i++) a |= ei[2 * i + 1];
        g_is64_ei = (a == 0) ? 1 : 0;
        unsigned b = 0;
        for (int i = 0; i < 32; i++) b |= ty[2 * i + 1];
        g_is64_ty = (b == 0) ? 1 : 0;
    }
}

// ---------------- fused setup: zero g_agg | pack w*g k-major | prep P -------
__global__ void __launch_bounds__(256) setup_kernel(
    const float* __restrict__ x, const float* __restrict__ emb,
    const float* __restrict__ w1, const float* __restrict__ b1,
    const void* __restrict__ ety, const float* __restrict__ w2g,
    const float* __restrict__ lng, int N) {
    int bid = blockIdx.x, t = threadIdx.x;
    int zb = N / 16;
    if (bid < zb) {
        ((float4*)g_agg)[bid * 256 + t] = make_float4(0.f, 0.f, 0.f, 0.f);
    } else if (bid < zb + 16) {
        int i = (bid - zb) * 256 + t;        // i = k*64 + d
        int k = i >> 6, d = i & 63;
        g_wgk[i] = w2g[d * 64 + k] * lng[k];
    } else {
        int nb = bid - zb - 16;
        int grp = t >> 6, d = t & 63;
        int n = nb * 4 + grp;
        __shared__ float xs[4][16];
        int is64 = g_is64_ty;
        if (d < 6) {
            xs[grp][d] = x[n * 6 + d];
        } else if (d < 14) {
            long tt = ldidx(ety, n, is64);
            xs[grp][d] = emb[tt * 8 + (d - 6)];
        }
        __syncthreads();
        float acc = b1[d];
#pragma unroll
        for (int k = 0; k < 14; k++) acc = fmaf(xs[grp][k], w1[d * 15 + k], acc);
        g_P[n * HID + d] = acc;
    }
}

// ---------------- edge MLP + scatter-add: 2 tiles of 128 edges per block ----
// Weights staged once per block at dyn+33280 (PAST the 33,280-byte outb
// overlay footprint -> no cross-tile corruption). Per tile: thread-per-edge
// stage A, broadcast f32x2 GEMM, two-pass LN2 + coalesced cooperative red.
#define EDGE_DYN (33280 + 16384)
__global__ void __launch_bounds__(128, 4) edge_kernel(
    const void* __restrict__ ei, const float* __restrict__ eattr,
    const float* __restrict__ w1, const float* __restrict__ lng,
    const float* __restrict__ lnb, int nE) {
    extern __shared__ __align__(16) char dyn[];
    float* h1f = (float*)dyn;                 // 32KB [k][128]; outb overlay 33,280B
    float* w2s = (float*)(dyn + 33280);       // 16KB [k][64] scalar w*g (persistent)
    __shared__ __align__(16) float w1ls[64];
    __shared__ __align__(16) float As[64];
    __shared__ __align__(16) float Bcs[64];
    __shared__ __align__(16) float gs[64];
    __shared__ __align__(16) float bs[64];
    __shared__ __align__(8) float rst[128 * 2];
    __shared__ int sdst[128];

    int tid = threadIdx.x;
    {   // stage scalar weights once: 1024 float4 over 128 threads
        const float4* wsrc = (const float4*)g_wgk;
        float4* wdst = (float4*)w2s;
#pragma unroll
        for (int i = 0; i < 8; i++) wdst[i * 128 + tid] = wsrc[i * 128 + tid];
    }
    if (tid < 64) {
        w1ls[tid] = w1[tid * 15 + 14];
        As[tid] = g_A[tid];
        Bcs[tid] = g_Bc[tid];
        gs[tid] = lng[tid];
        bs[tid] = lnb[tid];
    }
    int is64 = g_is64_ei;
    int lane = tid & 31, wrp = tid >> 5;

    for (int tile = 0; tile < 2; tile++) {
        long e = (long)blockIdx.x * 256 + tile * 128 + tid;
        bool act = e < nE;
        long src = 0;
        float a = 0.f;
        long dl = -1;
        if (act) {
            src = ldidx(ei, e, is64);
            dl = ldidx(ei, (long)nE + e, is64);
            a = eattr[e];
        }
        __syncthreads();   // prev tile fully done (red reads of outb/sdst)
        sdst[tid] = (int)dl;

        // ---- Stage A: x = relu(P[src] + a*w1_last); in-thread stats ----
        {
            const float4* pr = (const float4*)(g_P + src * 64);
            float s1 = 0.f, q1 = 0.f;
#pragma unroll
            for (int g = 0; g < 16; g++) {
                float4 p = pr[g];
                float4 wl = ((const float4*)w1ls)[g];
                float x0 = fmaxf(fmaf(a, wl.x, p.x), 0.f);
                float x1 = fmaxf(fmaf(a, wl.y, p.y), 0.f);
                float x2 = fmaxf(fmaf(a, wl.z, p.z), 0.f);
                float x3 = fmaxf(fmaf(a, wl.w, p.w), 0.f);
                h1f[(4 * g + 0) * 128 + tid] = x0;
                h1f[(4 * g + 1) * 128 + tid] = x1;
                h1f[(4 * g + 2) * 128 + tid] = x2;
                h1f[(4 * g + 3) * 128 + tid] = x3;
                s1 += (x0 + x1) + (x2 + x3);
                q1 = fmaf(x0, x0, q1); q1 = fmaf(x1, x1, q1);
                q1 = fmaf(x2, x2, q1); q1 = fmaf(x3, x3, q1);
            }
            float mean1 = s1 * (1.f / 64.f);
            float var1 = fmaf(-mean1, mean1, q1 * (1.f / 64.f));
            float r1 = rsqrtf(var1 + 1e-5f);
            rst[2 * tid] = r1;
            rst[2 * tid + 1] = -mean1 * r1;
        }
        __syncthreads();

        // ---- Stage B: acc over dim-pairs; w pairs native, h duplicated ----
        ull acc[4][8];
#pragma unroll
        for (int ee = 0; ee < 4; ee++)
#pragma unroll
            for (int jp = 0; jp < 8; jp++) acc[ee][jp] = 0ull;
        {
            const float4* hb4 = (const float4*)h1f;
            const float* wbase = w2s + wrp * 16;
#pragma unroll 8
            for (int k = 0; k < 64; k++) {
                float4 hv = hb4[k * 32 + lane];
                ull h0 = pack2(hv.x, hv.x);
                ull h1 = pack2(hv.y, hv.y);
                ull h2 = pack2(hv.z, hv.z);
                ull h3 = pack2(hv.w, hv.w);
                const ulonglong2* wk = (const ulonglong2*)(wbase + k * 64);
                ulonglong2 wA = wk[0];
                ulonglong2 wB = wk[1];
                ulonglong2 wC = wk[2];
                ulonglong2 wD = wk[3];
                ffma2(acc[0][0], wA.x, h0); ffma2(acc[1][0], wA.x, h1);
                ffma2(acc[2][0], wA.x, h2); ffma2(acc[3][0], wA.x, h3);
                ffma2(acc[0][1], wA.y, h0); ffma2(acc[1][1], wA.y, h1);
                ffma2(acc[2][1], wA.y, h2); ffma2(acc[3][1], wA.y, h3);
                ffma2(acc[0][2], wB.x, h0); ffma2(acc[1][2], wB.x, h1);
                ffma2(acc[2][2], wB.x, h2); ffma2(acc[3][2], wB.x, h3);
                ffma2(acc[0][3], wB.y, h0); ffma2(acc[1][3], wB.y, h1);
                ffma2(acc[2][3], wB.y, h2); ffma2(acc[3][3], wB.y, h3);
                ffma2(acc[0][4], wC.x, h0); ffma2(acc[1][4], wC.x, h1);
                ffma2(acc[2][4], wC.x, h2); ffma2(acc[3][4], wC.x, h3);
                ffma2(acc[0][5], wC.y, h0); ffma2(acc[1][5], wC.y, h1);
                ffma2(acc[2][5], wC.y, h2); ffma2(acc[3][5], wC.y, h3);
                ffma2(acc[0][6], wD.x, h0); ffma2(acc[1][6], wD.x, h1);
                ffma2(acc[2][6], wD.x, h2); ffma2(acc[3][6], wD.x, h3);
                ffma2(acc[0][7], wD.y, h0); ffma2(acc[1][7], wD.y, h1);
                ffma2(acc[2][7], wD.y, h2); ffma2(acc[3][7], wD.y, h3);
            }
        }

        // ---- Stage C (two-pass) ----
        float Ar[16], Br[16];
        {
            const float4* ap = (const float4*)(As + wrp * 16);
            const float4* bp = (const float4*)(Bcs + wrp * 16);
#pragma unroll
            for (int u = 0; u < 4; u++) {
                float4 av = ap[u], bv = bp[u];
                Ar[4 * u] = av.x; Ar[4 * u + 1] = av.y;
                Ar[4 * u + 2] = av.z; Ar[4 * u + 3] = av.w;
                Br[4 * u] = bv.x; Br[4 * u + 1] = bv.y;
                Br[4 * u + 2] = bv.z; Br[4 * u + 3] = bv.w;
            }
        }
        float rr[4], mm[4];
#pragma unroll
        for (int i = 0; i < 4; i++) {
            rr[i] = rst[2 * (4 * lane + i)];
            mm[i] = rst[2 * (4 * lane + i) + 1];
        }
        float se[4] = {0.f, 0.f, 0.f, 0.f}, qe[4] = {0.f, 0.f, 0.f, 0.f};
#pragma unroll
        for (int ee = 0; ee < 4; ee++) {
#pragma unroll
            for (int jp = 0; jp < 8; jp++) {
                float lo, hi;
                unpack2(acc[ee][jp], lo, hi);
                int j0 = 2 * jp, j1 = 2 * jp + 1;
                float v0 = fmaxf(fmaf(rr[ee], lo, fmaf(mm[ee], Ar[j0], Br[j0])), 0.f);
                float v1 = fmaxf(fmaf(rr[ee], hi, fmaf(mm[ee], Ar[j1], Br[j1])), 0.f);
                se[ee] += v0 + v1;
                qe[ee] = fmaf(v0, v0, qe[ee]);
                qe[ee] = fmaf(v1, v1, qe[ee]);
            }
        }
        __syncthreads();   // h1f reads done; overlay partials
        float* ps = h1f;
        float* pq = h1f + 512;
#pragma unroll
        for (int i = 0; i < 4; i++) {
            ps[wrp * 128 + 4 * lane + i] = se[i];
            pq[wrp * 128 + 4 * lane + i] = qe[i];
        }
        __syncthreads();
        {
            float s = ps[tid] + ps[128 + tid] + ps[256 + tid] + ps[384 + tid];
            float q = pq[tid] + pq[128 + tid] + pq[256 + tid] + pq[384 + tid];
            float mean = s * (1.f / 64.f);
            float var = fmaf(-mean, mean, q * (1.f / 64.f));
            float r = rsqrtf(var + 1e-5f);
            rst[2 * tid] = r;
            rst[2 * tid + 1] = -mean * r;
        }
        __syncthreads();
        float* outb = (float*)dyn;
#pragma unroll
        for (int ee = 0; ee < 4; ee++) {
            int eIdx = 4 * lane + ee;
            float r2 = rst[2 * eIdx];
            float mr2 = rst[2 * eIdx + 1];
            float* orow = outb + eIdx * 65 + wrp * 16;
#pragma unroll
            for (int u = 0; u < 4; u++) {
                int jpA = 2 * u, jpB = 2 * u + 1;
                float lo0, hi0, lo1, hi1;
                unpack2(acc[ee][jpA], lo0, hi0);
                unpack2(acc[ee][jpB], lo1, hi1);
                int j0 = 4 * u, j1 = j0 + 1, j2 = j0 + 2, j3 = j0 + 3;
                float v0 = fmaxf(fmaf(rr[ee], lo0, fmaf(mm[ee], Ar[j0], Br[j0])), 0.f);
                float v1 = fmaxf(fmaf(rr[ee], hi0, fmaf(mm[ee], Ar[j1], Br[j1])), 0.f);
                float v2 = fmaxf(fmaf(rr[ee], lo1, fmaf(mm[ee], Ar[j2], Br[j2])), 0.f);
                float v3 = fmaxf(fmaf(rr[ee], hi1, fmaf(mm[ee], Ar[j3], Br[j3])), 0.f);
                float4 gv = ((const float4*)(gs + wrp * 16))[u];
                float4 bv = ((const float4*)(bs + wrp * 16))[u];
                orow[4 * u + 0] = fmaf(fmaf(v0, r2, mr2), gv.x, bv.x);
                orow[4 * u + 1] = fmaf(fmaf(v1, r2, mr2), gv.y, bv.y);
                orow[4 * u + 2] = fmaf(fmaf(v2, r2, mr2), gv.z, bv.z);
                orow[4 * u + 3] = fmaf(fmaf(v3, r2, mr2), gv.w, bv.w);
            }
        }
        __syncthreads();
        {
            int ce = tid >> 4;
            int cc = tid & 15;
#pragma unroll
            for (int i = 0; i < 16; i++) {
                int eIdx = i * 8 + ce;
                int dnL = sdst[eIdx];
                const float* orow = outb + eIdx * 65 + 4 * cc;
                float o0 = orow[0], o1 = orow[1], o2 = orow[2], o3 = orow[3];
                if (dnL >= 0) {
                    float* p = g_agg + (long)dnL * 64 + 4 * cc;
                    asm volatile("red.global.add.v4.f32 [%0], {%1,%2,%3,%4};"
                                 :: "l"(p), "f"(o0), "f"(o1), "f"(o2), "f"(o3)
                                 : "memory");
                }
            }
        }
    }
}

// ---------------- qkv = h @ in_proj_w.T + b, 32 nodes/block ------------------
__global__ void __launch_bounds__(192) qkv_kernel(const float* __restrict__ w,
                                                  const float* __restrict__ b, int N) {
    __shared__ __align__(16) float hs[32 * 64];
    int tid = threadIdx.x;
    int n0 = blockIdx.x * 32;
    for (int i = tid; i < 32 * 64 / 4; i += 192)
        ((float4*)hs)[i] = ((const float4*)(g_agg + n0 * 64))[i];
    float wr[64];
    {
        const float4* p4 = (const float4*)(w + tid * 64);
#pragma unroll
        for (int k = 0; k < 16; k++) {
            float4 f = p4[k];
            wr[4 * k] = f.x; wr[4 * k + 1] = f.y; wr[4 * k + 2] = f.z; wr[4 * k + 3] = f.w;
        }
    }
    float br = b[tid];
    __syncthreads();
    int sec = tid / 64, wi = tid % 64, hh = wi / 16, dd = wi % 16;
    float* dst = sec == 0 ? g_q : (sec == 1 ? g_k : g_v);
#pragma unroll 4
    for (int nn = 0; nn < 32; nn++) {
        float acc = br;
#pragma unroll
        for (int k = 0; k < 16; k++) {
            float4 h = *(const float4*)&hs[nn * 64 + 4 * k];
            acc = fmaf(wr[4 * k], h.x, acc);
            acc = fmaf(wr[4 * k + 1], h.y, acc);
            acc = fmaf(wr[4 * k + 2], h.z, acc);
            acc = fmaf(wr[4 * k + 3], h.w, acc);
        }
        dst[hh * N * 16 + (n0 + nn) * 16 + dd] = acc;
    }
}

// ---------------- flash attention: 4 queries/thread, 4-way K-split ----------
__global__ void __launch_bounds__(128) attn_kernel(int N) {
    int hh = blockIdx.y;
    int part = threadIdx.x >> 5;
    int lane = threadIdx.x & 31;
    int qbase = blockIdx.x * 128 + lane;
    const float* Q = g_q + hh * N * 16;
    const float* K = g_k + hh * N * 16;
    const float* V = g_v + hh * N * 16;

    __shared__ __align__(16) float KV[8192];   // Ks [4][1024] | Vs [4][1024]
    float* Ks = KV + part * 1024;
    float* Vs = KV + 4096 + part * 1024;

    const float QS = 0.25f * 1.4426950408889634f;
    ull q0[8], q1[8], q2[8], q3[8];
    {
#pragma unroll
        for (int u = 0; u < 4; u++) {
            float4 f0 = ((const float4*)(Q + (qbase + 0) * 16))[u];
            float4 f1 = ((const float4*)(Q + (qbase + 32) * 16))[u];
            float4 f2 = ((const float4*)(Q + (qbase + 64) * 16))[u];
            float4 f3 = ((const float4*)(Q + (qbase + 96) * 16))[u];
            q0[2 * u] = pack2(f0.x * QS, f0.y * QS);
            q0[2 * u + 1] = pack2(f0.z * QS, f0.w * QS);
            q1[2 * u] = pack2(f1.x * QS, f1.y * QS);
            q1[2 * u + 1] = pack2(f1.z * QS, f1.w * QS);
            q2[2 * u] = pack2(f2.x * QS, f2.y * QS);
            q2[2 * u + 1] = pack2(f2.z * QS, f2.w * QS);
            q3[2 * u] = pack2(f3.x * QS, f3.y * QS);
            q3[2 * u + 1] = pack2(f3.z * QS, f3.w * QS);
        }
    }
    ull o0[8], o1[8], o2[8], o3[8];
#pragma unroll
    for (int u = 0; u < 8; u++) { o0[u] = 0ull; o1[u] = 0ull; o2[u] = 0ull; o3[u] = 0ull; }
    float m0 = -1e30f, m1 = -1e30f, m2 = -1e30f, m3 = -1e30f;
    float l0 = 0.f, l1 = 0.f, l2 = 0.f, l3 = 0.f;

    int jb = part * (N >> 2);
    for (int kt = 0; kt < (N >> 2); kt += 64) {
        {
            const float4* ksrc = (const float4*)(K + (jb + kt) * 16);
            const float4* vsrc = (const float4*)(V + (jb + kt) * 16);
            float4* kdst = (float4*)Ks;
            float4* vdst = (float4*)Vs;
#pragma unroll
            for (int u = 0; u < 8; u++) {
                kdst[u * 32 + lane] = ksrc[u * 32 + lane];
                vdst[u * 32 + lane] = vsrc[u * 32 + lane];
            }
        }
        __syncwarp();
        for (int c = 0; c < 8; c++) {
            float s0[8], s1[8], s2[8], s3[8];
#pragma unroll
            for (int jj = 0; jj < 8; jj++) {
                int j = c * 8 + jj;
                const ulonglong2* kr = (const ulonglong2*)&Ks[j * 16];
                ulonglong2 ka = kr[0], kb = kr[1], kc = kr[2], kd = kr[3];
                ull sa = mul2(q0[0], ka.x);
                ffma2(sa, q0[1], ka.y); ffma2(sa, q0[2], kb.x); ffma2(sa, q0[3], kb.y);
                ffma2(sa, q0[4], kc.x); ffma2(sa, q0[5], kc.y);
                ffma2(sa, q0[6], kd.x); ffma2(sa, q0[7], kd.y);
                ull sb = mul2(q1[0], ka.x);
                ffma2(sb, q1[1], ka.y); ffma2(sb, q1[2], kb.x); ffma2(sb, q1[3], kb.y);
                ffma2(sb, q1[4], kc.x); ffma2(sb, q1[5], kc.y);
                ffma2(sb, q1[6], kd.x); ffma2(sb, q1[7], kd.y);
                ull sc = mul2(q2[0], ka.x);
                ffma2(sc, q2[1], ka.y); ffma2(sc, q2[2], kb.x); ffma2(sc, q2[3], kb.y);
                ffma2(sc, q2[4], kc.x); ffma2(sc, q2[5], kc.y);
                ffma2(sc, q2[6], kd.x); ffma2(sc, q2[7], kd.y);
                ull sd = mul2(q3[0], ka.x);
                ffma2(sd, q3[1], ka.y); ffma2(sd, q3[2], kb.x); ffma2(sd, q3[3], kb.y);
                ffma2(sd, q3[4], kc.x); ffma2(sd, q3[5], kc.y);
                ffma2(sd, q3[6], kd.x); ffma2(sd, q3[7], kd.y);
                float lo, hi;
                unpack2(sa, lo, hi); s0[jj] = lo + hi;
                unpack2(sb, lo, hi); s1[jj] = lo + hi;
                unpack2(sc, lo, hi); s2[jj] = lo + hi;
                unpack2(sd, lo, hi); s3[jj] = lo + hi;
            }
            float t0 = s0[0], t1 = s1[0], t2 = s2[0], t3 = s3[0];
#pragma unroll
            for (int jj = 1; jj < 8; jj++) {
                t0 = fmaxf(t0, s0[jj]); t1 = fmaxf(t1, s1[jj]);
                t2 = fmaxf(t2, s2[jj]); t3 = fmaxf(t3, s3[jj]);
            }
            float n0 = fmaxf(m0, t0), n1 = fmaxf(m1, t1);
            float n2 = fmaxf(m2, t2), n3 = fmaxf(m3, t3);
            float c0 = ex2f(m0 - n0), c1 = ex2f(m1 - n1);
            float c2 = ex2f(m2 - n2), c3 = ex2f(m3 - n3);
            m0 = n0; m1 = n1; m2 = n2; m3 = n3;
            l0 *= c0; l1 *= c1; l2 *= c2; l3 *= c3;
            ull c02 = pack2(c0, c0), c12 = pack2(c1, c1);
            ull c22 = pack2(c2, c2), c32 = pack2(c3, c3);
#pragma unroll
            for (int u = 0; u < 8; u++) {
                o0[u] = mul2(o0[u], c02);
                o1[u] = mul2(o1[u], c12);
                o2[u] = mul2(o2[u], c22);
                o3[u] = mul2(o3[u], c32);
            }
#pragma unroll
            for (int jj = 0; jj < 8; jj++) {
                int j = c * 8 + jj;
                float p0 = ex2f(s0[jj] - m0);
                float p1 = ex2f(s1[jj] - m1);
                float p2 = ex2f(s2[jj] - m2);
                float p3 = ex2f(s3[jj] - m3);
                l0 += p0; l1 += p1; l2 += p2; l3 += p3;
                ull p02 = pack2(p0, p0), p12 = pack2(p1, p1);
                ull p22 = pack2(p2, p2), p32 = pack2(p3, p3);
                const ulonglong2* vr = (const ulonglong2*)&Vs[j * 16];
                ulonglong2 va = vr[0], vb = vr[1], vc = vr[2], vd = vr[3];
                ffma2(o0[0], p02, va.x); ffma2(o1[0], p12, va.x);
                ffma2(o2[0], p22, va.x); ffma2(o3[0], p32, va.x);
                ffma2(o0[1], p02, va.y); ffma2(o1[1], p12, va.y);
                ffma2(o2[1], p22, va.y); ffma2(o3[1], p32, va.y);
                ffma2(o0[2], p02, vb.x); ffma2(o1[2], p12, vb.x);
                ffma2(o2[2], p22, vb.x); ffma2(o3[2], p32, vb.x);
                ffma2(o0[3], p02, vb.y); ffma2(o1[3], p12, vb.y);
                ffma2(o2[3], p22, vb.y); ffma2(o3[3], p32, vb.y);
                ffma2(o0[4], p02, vc.x); ffma2(o1[4], p12, vc.x);
                ffma2(o2[4], p22, vc.x); ffma2(o3[4], p32, vc.x);
                ffma2(o0[5], p02, vc.y); ffma2(o1[5], p12, vc.y);
                ffma2(o2[5], p22, vc.y); ffma2(o3[5], p32, vc.y);
                ffma2(o0[6], p02, vd.x); ffma2(o1[6], p12, vd.x);
                ffma2(o2[6], p22, vd.x); ffma2(o3[6], p32, vd.x);
                ffma2(o0[7], p02, vd.y); ffma2(o1[7], p12, vd.y);
                ffma2(o2[7], p22, vd.y); ffma2(o3[7], p32, vd.y);
            }
        }
        __syncwarp();
    }

    // ---- merge: overlay mrg[3][128][18] onto dead Ks/Vs region ----
    __syncthreads();
    float* mrg = KV;
    if (part != 0) {
        float mq[4] = {m0, m1, m2, m3};
        float lq[4] = {l0, l1, l2, l3};
#pragma unroll
        for (int qq = 0; qq < 4; qq++) {
            ull* oq = qq == 0 ? o0 : (qq == 1 ? o1 : (qq == 2 ? o2 : o3));
            float* d = mrg + ((part - 1) * 128 + qq * 32 + lane) * 18;
            d[0] = mq[qq];
            d[1] = lq[qq];
#pragma unroll
            for (int u = 0; u < 8; u++) {
                float lo, hi;
                unpack2(oq[u], lo, hi);
                d[2 + 2 * u] = lo;
                d[3 + 2 * u] = hi;
            }
        }
    }
    __syncthreads();
    if (part == 0) {
        float mq[4] = {m0, m1, m2, m3};
        float lq[4] = {l0, l1, l2, l3};
#pragma unroll
        for (int qq = 0; qq < 4; qq++) {
            ull* oq = qq == 0 ? o0 : (qq == 1 ? o1 : (qq == 2 ? o2 : o3));
            int qslot = qq * 32 + lane;
            float M = mq[qq];
#pragma unroll
            for (int p2i = 0; p2i < 3; p2i++)
                M = fmaxf(M, mrg[(p2i * 128 + qslot) * 18]);
            float c0 = ex2f(mq[qq] - M);
            float L = lq[qq] * c0;
            float o[16];
#pragma unroll
            for (int u = 0; u < 8; u++) {
                float lo, hi;
                unpack2(oq[u], lo, hi);
                o[2 * u] = lo * c0;
                o[2 * u + 1] = hi * c0;
            }
#pragma unroll
            for (int p2i = 0; p2i < 3; p2i++) {
                const float* sp = mrg + (p2i * 128 + qslot) * 18;
                float cp = ex2f(sp[0] - M);
                L = fmaf(sp[1], cp, L);
#pragma unroll
                for (int cc = 0; cc < 16; cc++) o[cc] = fmaf(sp[2 + cc], cp, o[cc]);
            }
            float inv = 1.f / L;
            int qn = qbase + qq * 32;
#pragma unroll
            for (int cc = 0; cc < 16; cc++)
                g_obuf[qn * 64 + hh * 16 + cc] = o[cc] * inv;
        }
    }
}

// ---------------- out_proj + residual + LN + final linear --------------------
__global__ void __launch_bounds__(128) epi_kernel(
    const float* __restrict__ opw, const float* __restrict__ opb,
    const float* __restrict__ ang, const float* __restrict__ anb,
    const float* __restrict__ ow, const float* __restrict__ ob,
    float* __restrict__ out) {
    int tid = threadIdx.x;
    int d = tid & 63, g = tid >> 6;
    int n0 = blockIdx.x * 8;
    __shared__ __align__(16) float os[8 * 64];
    __shared__ __align__(16) float ts[8 * 64];
    __shared__ float ps[8][16], pq[8][16];
    __shared__ float mv[8][2];

    for (int i = tid; i < 8 * 64; i += 128) os[i] = g_obuf[n0 * 64 + i];
    float wr[64];
    {
        const float4* p4 = (const float4*)(opw + d * 64);
#pragma unroll
        for (int k = 0; k < 16; k++) {
            float4 f = p4[k];
            wr[4 * k] = f.x; wr[4 * k + 1] = f.y; wr[4 * k + 2] = f.z; wr[4 * k + 3] = f.w;
        }
    }
    float bb = opb[d];
    __syncthreads();
#pragma unroll
    for (int ni = 0; ni < 4; ni++) {
        int nn = g * 4 + ni;
        float acc = bb;
#pragma unroll
        for (int k = 0; k < 16; k++) {
            float4 h = *(const float4*)&os[nn * 64 + 4 * k];
            acc = fmaf(wr[4 * k], h.x, acc);
            acc = fmaf(wr[4 * k + 1], h.y, acc);
            acc = fmaf(wr[4 * k + 2], h.z, acc);
            acc = fmaf(wr[4 * k + 3], h.w, acc);
        }
        ts[nn * 64 + d] = g_agg[(n0 + nn) * 64 + d] + acc;
    }
    __syncthreads();
    {
        int n = tid >> 4, sg = tid & 15;
        float s = 0.f, qq = 0.f;
#pragma unroll
        for (int t = 0; t < 4; t++) {
            float v2 = ts[n * 64 + sg * 4 + t];
            s += v2; qq += v2 * v2;
        }
        ps[n][sg] = s; pq[n][sg] = qq;
    }
    __syncthreads();
    if (tid < 8) {
        float s = 0.f, qq = 0.f;
#pragma unroll
        for (int t = 0; t < 16; t++) { s += ps[tid][t]; qq += pq[tid][t]; }
        float mean = s * (1.f / 64.f);
        float var = qq * (1.f / 64.f) - mean * mean;
        mv[tid][0] = mean;
        mv[tid][1] = rsqrtf(var + 1e-5f);
    }
    __syncthreads();
    float gg = ang[d], gb = anb[d];
#pragma unroll
    for (int ni = 0; ni < 4; ni++) {
        int nn = g * 4 + ni;
        ts[nn * 64 + d] = (ts[nn * 64 + d] - mv[nn][0]) * mv[nn][1] * gg + gb;
    }
    {
        const float4* p4 = (const float4*)(ow + d * 64);
#pragma unroll
        for (int k = 0; k < 16; k++) {
            float4 f = p4[k];
            wr[4 * k] = f.x; wr[4 * k + 1] = f.y; wr[4 * k + 2] = f.z; wr[4 * k + 3] = f.w;
        }
    }
    float bo = ob[d];
    __syncthreads();
#pragma unroll
    for (int ni = 0; ni < 4; ni++) {
        int nn = g * 4 + ni;
        float acc = bo;
#pragma unroll
        for (int k = 0; k < 16; k++) {
            float4 h = *(const float4*)&ts[nn * 64 + 4 * k];
            acc = fmaf(wr[4 * k], h.x, acc);
            acc = fmaf(wr[4 * k + 1], h.y, acc);
            acc = fmaf(wr[4 * k + 2], h.z, acc);
            acc = fmaf(wr[4 * k + 3], h.w, acc);
        }
        out[(n0 + nn) * 64 + d] = acc;
    }
}

// ---------------- launch ----------------
extern "C" void kernel_launch(void* const* d_in, const int* in_sizes, int n_in,
                              void* d_out, int out_size) {
    const float* x        = (const float*)d_in[0];
    const float* eattr    = (const float*)d_in[1];
    const float* emb      = (const float*)d_in[2];
    const float* lin1_w   = (const float*)d_in[3];
    const float* lin1_b   = (const float*)d_in[4];
    const float* lay_w    = (const float*)d_in[5];
    const float* lay_b    = (const float*)d_in[6];
    const float* ln_g     = (const float*)d_in[7];
    const float* ln_b     = (const float*)d_in[8];
    const float* in_proj_w  = (const float*)d_in[9];
    const float* in_proj_b  = (const float*)d_in[10];
    const float* out_proj_w = (const float*)d_in[11];
    const float* out_proj_b = (const float*)d_in[12];
    const float* an_g     = (const float*)d_in[13];
    const float* an_b     = (const float*)d_in[14];
    const float* out_w    = (const float*)d_in[15];
    const float* out_b    = (const float*)d_in[16];
    const void*  ei       = d_in[17];
    const void*  ety      = d_in[18];

    int E = in_sizes[1];
    int N = in_sizes[0] / 6;

    cudaFuncSetAttribute(edge_kernel, cudaFuncAttributeMaxDynamicSharedMemorySize,
                         EDGE_DYN);

    detectAB_kernel<<<1, 64>>>((const unsigned*)ei, (const unsigned*)ety,
                               lay_w, ln_g, ln_b, lay_b);
    setup_kernel<<<N / 16 + 16 + N / 4, 256>>>(x, emb, lin1_w, lin1_b, ety,
                                               lay_w, ln_g, N);
    edge_kernel<<<(E + 255) / 256, 128, EDGE_DYN>>>(ei, eattr, lin1_w, ln_g,
                                                    ln_b, E);
    qkv_kernel<<<N / 32, 192>>>(in_proj_w, in_proj_b, N);
    attn_kernel<<<dim3(N / 128, 4), 128>>>(N);
    epi_kernel<<<N / 8, 128>>>(out_proj_w, out_proj_b, an_g, an_b, out_w, out_b,
                               (float*)d_out);
}